// round 1
// baseline (speedup 1.0000x reference)
#include <cuda_runtime.h>
#include <math.h>

#define B_   2
#define T_   2048
#define DM_  512
#define H_   8
#define D_   64
#define BH_  (B_*H_)
#define U_   3      // int(0.4 * ln(2048)) = 3 selected queries per (b,h)

// ---------------- scratch (static device allocations; no cudaMalloc) ----------------
__device__ float g_Q[B_*T_*DM_];    // 8 MB projected Q, layout [(b*T+t)][h*D+d]
__device__ float g_K[B_*T_*DM_];    // 8 MB
__device__ float g_V[B_*T_*DM_];    // 8 MB
__device__ float g_KL[BH_*T_];      // KL score per (b,h,q)
__device__ int   g_top[BH_*U_];     // top-3 query indices per (b,h)
__device__ float g_att[BH_*U_*D_];  // reduced attention outputs

// =====================================================================
// Projection GEMM:  Y[M=4096][512] = X[4096][512] @ W^T + bias
// W row-major [512][512]; reduction over W's row elements (NT gemm).
// BM=128, BN=64, BK=32, 256 threads, per-thread 8x4, float4 dot form.
// =====================================================================
__global__ __launch_bounds__(256) void proj_kernel(
    const float* __restrict__ X, const float* __restrict__ W,
    const float* __restrict__ bias, float* __restrict__ Y)
{
    __shared__ float Xs[128][36];   // pad to 36 floats (144B, 16B aligned)
    __shared__ float Ws[64][36];
    const int m0 = blockIdx.x * 128;
    const int n0 = blockIdx.y * 64;
    const int tid = threadIdx.x;
    const int tx = tid & 15;        // n group (4 cols)
    const int ty = tid >> 4;        // m group (8 rows)

    float acc[8][4];
#pragma unroll
    for (int i = 0; i < 8; i++)
#pragma unroll
        for (int j = 0; j < 4; j++) acc[i][j] = 0.f;

    for (int k0 = 0; k0 < DM_; k0 += 32) {
#pragma unroll
        for (int l = 0; l < 4; l++) {
            int idx = l * 256 + tid;
            int r = idx >> 3, c = (idx & 7) * 4;
            *(float4*)&Xs[r][c] = *(const float4*)&X[(size_t)(m0 + r) * DM_ + k0 + c];
        }
#pragma unroll
        for (int l = 0; l < 2; l++) {
            int idx = l * 256 + tid;
            int r = idx >> 3, c = (idx & 7) * 4;
            *(float4*)&Ws[r][c] = *(const float4*)&W[(size_t)(n0 + r) * DM_ + k0 + c];
        }
        __syncthreads();
#pragma unroll
        for (int dd = 0; dd < 8; dd++) {
            float4 a[8];
#pragma unroll
            for (int i = 0; i < 8; i++) a[i] = *(float4*)&Xs[ty * 8 + i][dd * 4];
#pragma unroll
            for (int j = 0; j < 4; j++) {
                float4 bb = *(float4*)&Ws[tx * 4 + j][dd * 4];
#pragma unroll
                for (int i = 0; i < 8; i++)
                    acc[i][j] += a[i].x * bb.x + a[i].y * bb.y + a[i].z * bb.z + a[i].w * bb.w;
            }
        }
        __syncthreads();
    }
#pragma unroll
    for (int i = 0; i < 8; i++) {
        int row = m0 + ty * 8 + i;
#pragma unroll
        for (int j = 0; j < 4; j++) {
            int col = n0 + tx * 4 + j;
            Y[(size_t)row * DM_ + col] = acc[i][j] + bias[col];
        }
    }
}

// =====================================================================
// KL kernel: per (b,h), streaming over all keys, per query row keep
// Z = sum exp(s), S = sum exp(s)*s  (s = q.k / 8, |s| ~ a few -> no max
// rescale needed in fp32).  KL = S/Z - log(Z) - log(1/T + 1e-10).
// BM=128 q-rows per CTA, BN=64 k per tile, D=64 full inner.
// Dynamic smem: Qs[128][68] + Ks[64][68] = 52224 B.
// =====================================================================
__global__ __launch_bounds__(256) void kl_kernel()
{
    extern __shared__ float s_kl[];
    float (*Qs)[68] = (float (*)[68])s_kl;
    float (*Ks)[68] = (float (*)[68])(s_kl + 128 * 68);

    const int bh = blockIdx.x;
    const int b = bh >> 3, h = bh & 7;
    const int q0 = blockIdx.y * 128;
    const int tid = threadIdx.x;
    const int tx = tid & 15;   // 4 k-cols
    const int ty = tid >> 4;   // 8 q-rows

    const float* Qbase = g_Q + (size_t)(b * T_) * DM_ + h * D_;
    const float* Kbase = g_K + (size_t)(b * T_) * DM_ + h * D_;

    // load Q tile once (128 rows x 64 d)
#pragma unroll
    for (int l = 0; l < 8; l++) {
        int idx = l * 256 + tid;
        int r = idx >> 4, c = (idx & 15) * 4;
        *(float4*)&Qs[r][c] = *(const float4*)&Qbase[(size_t)(q0 + r) * DM_ + c];
    }

    float Zr[8], Sr[8];
#pragma unroll
    for (int i = 0; i < 8; i++) { Zr[i] = 0.f; Sr[i] = 0.f; }

    for (int kt = 0; kt < T_; kt += 64) {
        __syncthreads();   // protect Ks (prev iter) — also orders first Ks load after Q load
#pragma unroll
        for (int l = 0; l < 4; l++) {
            int idx = l * 256 + tid;
            int r = idx >> 4, c = (idx & 15) * 4;
            *(float4*)&Ks[r][c] = *(const float4*)&Kbase[(size_t)(kt + r) * DM_ + c];
        }
        __syncthreads();

        float acc[8][4];
#pragma unroll
        for (int i = 0; i < 8; i++)
#pragma unroll
            for (int j = 0; j < 4; j++) acc[i][j] = 0.f;

#pragma unroll
        for (int dd = 0; dd < 16; dd++) {
            float4 a[8];
#pragma unroll
            for (int i = 0; i < 8; i++) a[i] = *(float4*)&Qs[ty * 8 + i][dd * 4];
#pragma unroll
            for (int j = 0; j < 4; j++) {
                float4 bb = *(float4*)&Ks[tx * 4 + j][dd * 4];
#pragma unroll
                for (int i = 0; i < 8; i++)
                    acc[i][j] += a[i].x * bb.x + a[i].y * bb.y + a[i].z * bb.z + a[i].w * bb.w;
            }
        }
#pragma unroll
        for (int i = 0; i < 8; i++)
#pragma unroll
            for (int j = 0; j < 4; j++) {
                float s = acc[i][j] * 0.125f;
                float e = __expf(s);
                Zr[i] += e;
                Sr[i] += e * s;
            }
    }

    // reduce across the 16 lanes sharing the same ty (contiguous 16 within warp)
    const float LOGU = logf(1.0f / (float)T_ + 1e-10f);
#pragma unroll
    for (int i = 0; i < 8; i++) {
        float z = Zr[i], s = Sr[i];
#pragma unroll
        for (int off = 1; off < 16; off <<= 1) {
            z += __shfl_xor_sync(0xffffffffu, z, off);
            s += __shfl_xor_sync(0xffffffffu, s, off);
        }
        if (tx == 0) {
            float lse = __logf(z);
            g_KL[bh * T_ + q0 + ty * 8 + i] = s / z - lse - LOGU;
        }
    }
}

// =====================================================================
// Top-3 per (b,h): 3 masked-argmax passes, ties -> lower index (jax-like)
// =====================================================================
__global__ __launch_bounds__(256) void topk_kernel()
{
    __shared__ float skl[T_];
    __shared__ float sv[256];
    __shared__ int   si[256];
    const int bh = blockIdx.x;
    const int tid = threadIdx.x;
    for (int i = tid; i < T_; i += 256) skl[i] = g_KL[bh * T_ + i];
    __syncthreads();
    for (int r = 0; r < U_; r++) {
        float bv = -1e30f; int bi = T_;
        for (int i = tid; i < T_; i += 256) {
            float v = skl[i];
            if (v > bv) { bv = v; bi = i; }
        }
        sv[tid] = bv; si[tid] = bi;
        __syncthreads();
        for (int st = 128; st > 0; st >>= 1) {
            if (tid < st) {
                float ov = sv[tid + st]; int oi = si[tid + st];
                if (ov > sv[tid] || (ov == sv[tid] && oi < si[tid])) { sv[tid] = ov; si[tid] = oi; }
            }
            __syncthreads();
        }
        if (tid == 0) { g_top[bh * U_ + r] = si[0]; skl[si[0]] = -1e30f; }
        __syncthreads();
    }
}

// =====================================================================
// Reduced attention: one CTA per (b,h,u). Full-precision softmax over
// all 2048 keys, then P@V with d-parallel accumulation.
// =====================================================================
__global__ __launch_bounds__(256) void sparse_attn_kernel()
{
    __shared__ float qs[64];
    __shared__ float sc[T_];
    __shared__ float red[8];
    __shared__ float ztot;
    __shared__ float pb[4][64];

    const int bid = blockIdx.x;           // 0..47
    const int bh = bid / U_;
    const int b = bh >> 3, h = bh & 7;
    const int t = g_top[bid];             // g_top[bh*U_+u] == g_top[bid]
    const int tid = threadIdx.x;
    const int warp = tid >> 5, lane = tid & 31;

    const float* Qb = g_Q + ((size_t)(b * T_) + t) * DM_ + h * D_;
    if (tid < 16) *(float4*)&qs[tid * 4] = *(const float4*)&Qb[tid * 4];
    __syncthreads();

    const float* Kb = g_K + (size_t)(b * T_) * DM_ + h * D_;
    const float q0 = qs[lane * 2], q1 = qs[lane * 2 + 1];
    float zp = 0.f;
    for (int k = warp; k < T_; k += 8) {
        float2 kv = *(const float2*)&Kb[(size_t)k * DM_ + lane * 2];
        float p = q0 * kv.x + q1 * kv.y;
#pragma unroll
        for (int off = 16; off > 0; off >>= 1) p += __shfl_xor_sync(0xffffffffu, p, off);
        if (lane == 0) {
            float s = p * 0.125f;
            if (!(s == s)) s = -10000.f;            // nan_to_num
            s = fminf(fmaxf(s, -10000.f), 10000.f); // clip
            float e = expf(s);
            sc[k] = e;
            zp += e;
        }
    }
    if (lane == 0) red[warp] = zp;
    __syncthreads();
    if (tid == 0) {
        float z = 0.f;
        for (int w = 0; w < 8; w++) z += red[w];
        ztot = z;
    }
    __syncthreads();
    const float invz = 1.f / ztot;

    const int d = tid & 63, c = tid >> 6;
    const float* Vb = g_V + (size_t)(b * T_) * DM_ + h * D_ + d;
    float o = 0.f;
    for (int k = c * 512; k < c * 512 + 512; k++) o += sc[k] * Vb[(size_t)k * DM_];
    pb[c][d] = o;
    __syncthreads();
    if (tid < 64)
        g_att[bid * 64 + tid] = (pb[0][tid] + pb[1][tid] + pb[2][tid] + pb[3][tid]) * invz;
}

// =====================================================================
// Output: fill with bo (scattered tensor is zero almost everywhere),
// then add the 48 selected-row contributions through Wo slices.
// =====================================================================
__global__ void init_out_kernel(float* __restrict__ out, const float* __restrict__ bo)
{
    int idx = blockIdx.x * 256 + threadIdx.x;
    if (idx < B_ * T_ * DM_) out[idx] = bo[idx & (DM_ - 1)];
}

__global__ __launch_bounds__(512) void scatter_kernel(
    const float* __restrict__ Wo, float* __restrict__ out)
{
    __shared__ float att[64];
    const int bid = blockIdx.x;      // 0..47
    const int bh = bid / U_;
    const int b = bh >> 3, h = bh & 7;
    const int t = g_top[bid];
    const int j = threadIdx.x;
    if (j < 16) *(float4*)&att[j * 4] = *(const float4*)&g_att[bid * 64 + j * 4];
    __syncthreads();
    const float* w = Wo + (size_t)j * DM_ + h * D_;
    float a = 0.f;
#pragma unroll
    for (int d = 0; d < 64; d++) a += att[d] * w[d];
    atomicAdd(&out[((size_t)b * T_ + t) * DM_ + j], a);  // heads may collide on same t
}

// =====================================================================
extern "C" void kernel_launch(void* const* d_in, const int* in_sizes, int n_in,
                              void* d_out, int out_size)
{
    const float* query = (const float*)d_in[0];
    const float* key   = (const float*)d_in[1];
    const float* value = (const float*)d_in[2];
    const float* Wq    = (const float*)d_in[3];
    const float* bq    = (const float*)d_in[4];
    const float* Wk    = (const float*)d_in[5];
    const float* bk    = (const float*)d_in[6];
    const float* Wv    = (const float*)d_in[7];
    const float* bv    = (const float*)d_in[8];
    const float* Wo    = (const float*)d_in[9];
    const float* bo    = (const float*)d_in[10];
    float* out = (float*)d_out;

    float *Qp, *Kp, *Vp;
    cudaGetSymbolAddress((void**)&Qp, g_Q);
    cudaGetSymbolAddress((void**)&Kp, g_K);
    cudaGetSymbolAddress((void**)&Vp, g_V);

    cudaFuncSetAttribute(kl_kernel, cudaFuncAttributeMaxDynamicSharedMemorySize,
                         (128 * 68 + 64 * 68) * 4);

    dim3 pg(32, 8);   // 4096/128 x 512/64
    proj_kernel<<<pg, 256>>>(query, Wq, bq, Qp);
    proj_kernel<<<pg, 256>>>(key,   Wk, bk, Kp);
    proj_kernel<<<pg, 256>>>(value, Wv, bv, Vp);

    dim3 kg(BH_, T_ / 128);  // (16, 16)
    kl_kernel<<<kg, 256, (128 * 68 + 64 * 68) * 4>>>();

    topk_kernel<<<BH_, 256>>>();
    sparse_attn_kernel<<<BH_ * U_, 256>>>();

    init_out_kernel<<<(B_ * T_ * DM_ + 255) / 256, 256>>>(out, bo);
    scatter_kernel<<<BH_ * U_, 512>>>(Wo, out);
}

// round 3
// speedup vs baseline: 1.5577x; 1.5577x over previous
#include <cuda_runtime.h>
#include <math.h>

#define B_   2
#define T_   2048
#define DM_  512
#define H_   8
#define D_   64
#define BH_  (B_*H_)
#define U_   3      // int(0.4 * ln(2048)) = 3 selected queries per (b,h)
#define KC_  2      // k-split for kl kernel

// ---------------- scratch (static device allocations; no cudaMalloc) ----------------
__device__ float g_Q[B_*T_*DM_];       // 8 MB projected Q, layout [(b*T+t)][h*D+d]
__device__ float g_K[B_*T_*DM_];       // 8 MB
__device__ float g_V[B_*T_*DM_];       // 8 MB
__device__ float g_Zp[KC_*BH_*T_];     // partial Z = sum exp(s)
__device__ float g_Sp[KC_*BH_*T_];     // partial S = sum exp(s)*s
__device__ int   g_top[BH_*U_];        // top-3 query indices per (b,h)
__device__ float g_att[BH_*U_*D_];     // reduced attention outputs

// =====================================================================
// Fused projection GEMMs:  Y = X @ W^T + bias, for (q,Wq),(k,Wk),(v,Wv)
// selected by blockIdx.z. M=4096, N=512, K=512.
// BM=BN=128, BK=16, 256 threads, 8x8 per thread, k-major smem tiles.
// =====================================================================
__global__ __launch_bounds__(256) void proj3_kernel(
    const float* __restrict__ q,  const float* __restrict__ k,  const float* __restrict__ v,
    const float* __restrict__ Wq, const float* __restrict__ Wk, const float* __restrict__ Wv,
    const float* __restrict__ bq, const float* __restrict__ bk, const float* __restrict__ bv,
    float* __restrict__ Qp, float* __restrict__ Kp, float* __restrict__ Vp)
{
    const float* X; const float* W; const float* bias; float* Y;
    if (blockIdx.z == 0)      { X = q; W = Wq; bias = bq; Y = Qp; }
    else if (blockIdx.z == 1) { X = k; W = Wk; bias = bk; Y = Kp; }
    else                      { X = v; W = Wv; bias = bv; Y = Vp; }

    __shared__ float As[16][132];   // k-major: As[k][m], 132*4=528 (16B aligned rows)
    __shared__ float Bs[16][132];   // k-major: Bs[k][n]

    const int m0 = blockIdx.x * 128;
    const int n0 = blockIdx.y * 128;
    const int tid = threadIdx.x;
    const int tx = tid & 15;        // n: 8 cols at tx*8
    const int ty = tid >> 4;        // m: 8 rows at ty*8
    const int lr = tid >> 2;        // 0..63  global-load row
    const int lc = (tid & 3) * 4;   // 0,4,8,12 global-load col

    float acc[8][8];
#pragma unroll
    for (int i = 0; i < 8; i++)
#pragma unroll
        for (int j = 0; j < 8; j++) acc[i][j] = 0.f;

    for (int k0 = 0; k0 < DM_; k0 += 16) {
        float4 x0 = *(const float4*)&X[(size_t)(m0 + lr)      * DM_ + k0 + lc];
        float4 x1 = *(const float4*)&X[(size_t)(m0 + lr + 64) * DM_ + k0 + lc];
        float4 w0 = *(const float4*)&W[(size_t)(n0 + lr)      * DM_ + k0 + lc];
        float4 w1 = *(const float4*)&W[(size_t)(n0 + lr + 64) * DM_ + k0 + lc];
        __syncthreads();   // previous tile fully consumed
        As[lc+0][lr] = x0.x; As[lc+1][lr] = x0.y; As[lc+2][lr] = x0.z; As[lc+3][lr] = x0.w;
        As[lc+0][lr+64] = x1.x; As[lc+1][lr+64] = x1.y; As[lc+2][lr+64] = x1.z; As[lc+3][lr+64] = x1.w;
        Bs[lc+0][lr] = w0.x; Bs[lc+1][lr] = w0.y; Bs[lc+2][lr] = w0.z; Bs[lc+3][lr] = w0.w;
        Bs[lc+0][lr+64] = w1.x; Bs[lc+1][lr+64] = w1.y; Bs[lc+2][lr+64] = w1.z; Bs[lc+3][lr+64] = w1.w;
        __syncthreads();

#pragma unroll
        for (int kk = 0; kk < 16; kk++) {
            float4 a0 = *(float4*)&As[kk][ty * 8];
            float4 a1 = *(float4*)&As[kk][ty * 8 + 4];
            float4 b0 = *(float4*)&Bs[kk][tx * 8];
            float4 b1 = *(float4*)&Bs[kk][tx * 8 + 4];
            float a[8] = {a0.x,a0.y,a0.z,a0.w,a1.x,a1.y,a1.z,a1.w};
            float b[8] = {b0.x,b0.y,b0.z,b0.w,b1.x,b1.y,b1.z,b1.w};
#pragma unroll
            for (int i = 0; i < 8; i++)
#pragma unroll
                for (int j = 0; j < 8; j++) acc[i][j] += a[i] * b[j];
        }
    }

    float bb[8];
#pragma unroll
    for (int j = 0; j < 8; j++) bb[j] = bias[n0 + tx * 8 + j];
#pragma unroll
    for (int i = 0; i < 8; i++) {
        int row = m0 + ty * 8 + i;
        float4 o0 = make_float4(acc[i][0]+bb[0], acc[i][1]+bb[1], acc[i][2]+bb[2], acc[i][3]+bb[3]);
        float4 o1 = make_float4(acc[i][4]+bb[4], acc[i][5]+bb[5], acc[i][6]+bb[6], acc[i][7]+bb[7]);
        *(float4*)&Y[(size_t)row * DM_ + n0 + tx * 8]     = o0;
        *(float4*)&Y[(size_t)row * DM_ + n0 + tx * 8 + 4] = o1;
    }
}

// =====================================================================
// KL accumulators: per (bh, q-tile of 128, k-half of 1024):
// streaming Z = sum exp(s), S = sum exp(s)*s over the k-half.
// 128x128 score tiles, 8x8 per thread, d-major smem (Qs[d][q], Ks[d][k]).
// Dynamic smem: 2 * 64 * 132 * 4 = 67584 B.
// =====================================================================
__global__ __launch_bounds__(256) void kl_kernel()
{
    extern __shared__ float sm[];
    float (*Qs)[132] = (float (*)[132])sm;
    float (*Ks)[132] = (float (*)[132])(sm + 64 * 132);

    const int bh = blockIdx.x;
    const int b = bh >> 3, h = bh & 7;
    const int q0 = blockIdx.y * 128;
    const int kc = blockIdx.z;
    const int kbase = kc * (T_ / KC_);
    const int tid = threadIdx.x;
    const int tx = tid & 15;
    const int ty = tid >> 4;
    const int lr = tid >> 2;        // 0..63
    const int lc = (tid & 3) * 4;   // 0,4,8,12

    const float* Qb = g_Q + (size_t)(b * T_) * DM_ + h * D_;
    const float* Kb = g_K + (size_t)(b * T_) * DM_ + h * D_;

    // load Q tile (128 q-rows x 64 d) transposed into Qs[d][q]
#pragma unroll
    for (int half = 0; half < 2; half++) {
        int r = lr + half * 64;
#pragma unroll
        for (int ic = 0; ic < 4; ic++) {
            int c = lc + ic * 16;
            float4 t = *(const float4*)&Qb[(size_t)(q0 + r) * DM_ + c];
            Qs[c+0][r] = t.x; Qs[c+1][r] = t.y; Qs[c+2][r] = t.z; Qs[c+3][r] = t.w;
        }
    }

    float Zr[8], Sr[8];
#pragma unroll
    for (int i = 0; i < 8; i++) { Zr[i] = 0.f; Sr[i] = 0.f; }

    for (int kt = 0; kt < T_ / KC_; kt += 128) {
        // prefetch half of K tile before the overwrite-barrier
        float4 p0[4];
#pragma unroll
        for (int ic = 0; ic < 4; ic++)
            p0[ic] = *(const float4*)&Kb[(size_t)(kbase + kt + lr) * DM_ + lc + ic * 16];
        __syncthreads();   // prev tile consumed (also orders initial Qs stores)
#pragma unroll
        for (int ic = 0; ic < 4; ic++) {
            int c = lc + ic * 16;
            Ks[c+0][lr] = p0[ic].x; Ks[c+1][lr] = p0[ic].y; Ks[c+2][lr] = p0[ic].z; Ks[c+3][lr] = p0[ic].w;
        }
#pragma unroll
        for (int ic = 0; ic < 4; ic++) {
            int c = lc + ic * 16;
            float4 t = *(const float4*)&Kb[(size_t)(kbase + kt + lr + 64) * DM_ + c];
            Ks[c+0][lr+64] = t.x; Ks[c+1][lr+64] = t.y; Ks[c+2][lr+64] = t.z; Ks[c+3][lr+64] = t.w;
        }
        __syncthreads();

        float acc[8][8];
#pragma unroll
        for (int i = 0; i < 8; i++)
#pragma unroll
            for (int j = 0; j < 8; j++) acc[i][j] = 0.f;

#pragma unroll 16
        for (int dd = 0; dd < 64; dd++) {
            float4 a0 = *(float4*)&Qs[dd][ty * 8];
            float4 a1 = *(float4*)&Qs[dd][ty * 8 + 4];
            float4 b0 = *(float4*)&Ks[dd][tx * 8];
            float4 b1 = *(float4*)&Ks[dd][tx * 8 + 4];
            float a[8] = {a0.x,a0.y,a0.z,a0.w,a1.x,a1.y,a1.z,a1.w};
            float bf[8] = {b0.x,b0.y,b0.z,b0.w,b1.x,b1.y,b1.z,b1.w};
#pragma unroll
            for (int i = 0; i < 8; i++)
#pragma unroll
                for (int j = 0; j < 8; j++) acc[i][j] += a[i] * bf[j];
        }

#pragma unroll
        for (int i = 0; i < 8; i++)
#pragma unroll
            for (int j = 0; j < 8; j++) {
                float s = acc[i][j] * 0.125f;
                float e = __expf(s);
                Zr[i] += e;
                Sr[i] += e * s;
            }
    }

    // reduce across the 16 tx-lanes sharing each ty (low 4 lane bits)
#pragma unroll
    for (int i = 0; i < 8; i++) {
        float z = Zr[i], s = Sr[i];
#pragma unroll
        for (int off = 1; off < 16; off <<= 1) {
            z += __shfl_xor_sync(0xffffffffu, z, off);
            s += __shfl_xor_sync(0xffffffffu, s, off);
        }
        if (tx == 0) {
            int qi = q0 + ty * 8 + i;
            g_Zp[(kc * BH_ + bh) * T_ + qi] = z;
            g_Sp[(kc * BH_ + bh) * T_ + qi] = s;
        }
    }
}

// =====================================================================
// Top-3 per (b,h): combine partials -> KL, then 3 masked-argmax passes.
// Ties -> lower index (jax-like).
// =====================================================================
__global__ __launch_bounds__(256) void topk_kernel()
{
    __shared__ float skl[T_];
    __shared__ float sv[256];
    __shared__ int   si[256];
    const int bh = blockIdx.x;
    const int tid = threadIdx.x;
    const float LOGU = logf(1.0f / (float)T_ + 1e-10f);
    for (int i = tid; i < T_; i += 256) {
        float z = g_Zp[bh * T_ + i] + g_Zp[(BH_ + bh) * T_ + i];
        float s = g_Sp[bh * T_ + i] + g_Sp[(BH_ + bh) * T_ + i];
        skl[i] = s / z - __logf(z) - LOGU;
    }
    __syncthreads();
    for (int r = 0; r < U_; r++) {
        float bv = -1e30f; int bi = T_;
        for (int i = tid; i < T_; i += 256) {
            float v = skl[i];
            if (v > bv) { bv = v; bi = i; }
        }
        sv[tid] = bv; si[tid] = bi;
        __syncthreads();
        for (int st = 128; st > 0; st >>= 1) {
            if (tid < st) {
                float ov = sv[tid + st]; int oi = si[tid + st];
                if (ov > sv[tid] || (ov == sv[tid] && oi < si[tid])) { sv[tid] = ov; si[tid] = oi; }
            }
            __syncthreads();
        }
        if (tid == 0) { g_top[bh * U_ + r] = si[0]; skl[si[0]] = -1e30f; }
        __syncthreads();
    }
}

// =====================================================================
// Reduced attention: one CTA per (b,h,u). Full softmax over 2048 keys,
// then P@V with d-parallel accumulation.
// =====================================================================
__global__ __launch_bounds__(256) void sparse_attn_kernel()
{
    __shared__ float qs[64];
    __shared__ float sc[T_];
    __shared__ float red[8];
    __shared__ float ztot;
    __shared__ float pb[4][64];

    const int bid = blockIdx.x;           // 0..47
    const int bh = bid / U_;
    const int b = bh >> 3, h = bh & 7;
    const int t = g_top[bid];
    const int tid = threadIdx.x;
    const int warp = tid >> 5, lane = tid & 31;

    const float* Qb = g_Q + ((size_t)(b * T_) + t) * DM_ + h * D_;
    if (tid < 16) *(float4*)&qs[tid * 4] = *(const float4*)&Qb[tid * 4];
    __syncthreads();

    const float* Kb = g_K + (size_t)(b * T_) * DM_ + h * D_;
    const float q0 = qs[lane * 2], q1 = qs[lane * 2 + 1];
    float zp = 0.f;
    for (int k = warp; k < T_; k += 8) {
        float2 kv = *(const float2*)&Kb[(size_t)k * DM_ + lane * 2];
        float p = q0 * kv.x + q1 * kv.y;
#pragma unroll
        for (int off = 16; off > 0; off >>= 1) p += __shfl_xor_sync(0xffffffffu, p, off);
        if (lane == 0) {
            float s = p * 0.125f;
            if (!(s == s)) s = -10000.f;
            s = fminf(fmaxf(s, -10000.f), 10000.f);
            float e = expf(s);
            sc[k] = e;
            zp += e;
        }
    }
    if (lane == 0) red[warp] = zp;
    __syncthreads();
    if (tid == 0) {
        float z = 0.f;
        for (int w = 0; w < 8; w++) z += red[w];
        ztot = z;
    }
    __syncthreads();
    const float invz = 1.f / ztot;

    const int d = tid & 63, c = tid >> 6;
    const float* Vb = g_V + (size_t)(b * T_) * DM_ + h * D_ + d;
    float o = 0.f;
    for (int k = c * 512; k < c * 512 + 512; k++) o += sc[k] * Vb[(size_t)k * DM_];
    pb[c][d] = o;
    __syncthreads();
    if (tid < 64)
        g_att[bid * 64 + tid] = (pb[0][tid] + pb[1][tid] + pb[2][tid] + pb[3][tid]) * invz;
}

// =====================================================================
// Output: fill with bo, then add the 48 selected-row contributions.
// =====================================================================
__global__ void init_out_kernel(float* __restrict__ out, const float* __restrict__ bo)
{
    int idx = blockIdx.x * 256 + threadIdx.x;
    if (idx < B_ * T_ * DM_) out[idx] = bo[idx & (DM_ - 1)];
}

__global__ __launch_bounds__(512) void scatter_kernel(
    const float* __restrict__ Wo, float* __restrict__ out)
{
    __shared__ float att[64];
    const int bid = blockIdx.x;      // 0..47
    const int bh = bid / U_;
    const int b = bh >> 3, h = bh & 7;
    const int t = g_top[bid];
    const int j = threadIdx.x;
    if (j < 16) *(float4*)&att[j * 4] = *(const float4*)&g_att[bid * 64 + j * 4];
    __syncthreads();
    const float* w = Wo + (size_t)j * DM_ + h * D_;
    float a = 0.f;
#pragma unroll
    for (int d = 0; d < 64; d++) a += att[d] * w[d];
    atomicAdd(&out[((size_t)b * T_ + t) * DM_ + j], a);
}

// =====================================================================
extern "C" void kernel_launch(void* const* d_in, const int* in_sizes, int n_in,
                              void* d_out, int out_size)
{
    const float* query = (const float*)d_in[0];
    const float* key   = (const float*)d_in[1];
    const float* value = (const float*)d_in[2];
    const float* Wq    = (const float*)d_in[3];
    const float* bq    = (const float*)d_in[4];
    const float* Wk    = (const float*)d_in[5];
    const float* bk    = (const float*)d_in[6];
    const float* Wv    = (const float*)d_in[7];
    const float* bv    = (const float*)d_in[8];
    const float* Wo    = (const float*)d_in[9];
    const float* bo    = (const float*)d_in[10];
    float* out = (float*)d_out;

    float *Qp, *Kp, *Vp;
    cudaGetSymbolAddress((void**)&Qp, g_Q);
    cudaGetSymbolAddress((void**)&Kp, g_K);
    cudaGetSymbolAddress((void**)&Vp, g_V);

    cudaFuncSetAttribute(kl_kernel, cudaFuncAttributeMaxDynamicSharedMemorySize,
                         2 * 64 * 132 * 4);

    dim3 pg(32, 4, 3);   // 4096/128 x 512/128 x {q,k,v}
    proj3_kernel<<<pg, 256>>>(query, key, value, Wq, Wk, Wv, bq, bk, bv, Qp, Kp, Vp);

    dim3 kg(BH_, T_ / 128, KC_);  // (16, 16, 2)
    kl_kernel<<<kg, 256, 2 * 64 * 132 * 4>>>();

    topk_kernel<<<BH_, 256>>>();
    sparse_attn_kernel<<<BH_ * U_, 256>>>();

    init_out_kernel<<<(B_ * T_ * DM_ + 255) / 256, 256>>>(out, bo);
    scatter_kernel<<<BH_ * U_, 512>>>(Wo, out);
}

// round 4
// speedup vs baseline: 1.7931x; 1.1511x over previous
#include <cuda_runtime.h>
#include <math.h>

#define B_   2
#define T_   2048
#define DM_  512
#define H_   8
#define D_   64
#define BH_  (B_*H_)
#define U_   3      // int(0.4 * ln(2048)) = 3 selected queries per (b,h)
#define KC_  2      // k-split for kl kernel
#define NCH_ 8      // key-chunk split for sparse attention (2048/8 = 256 keys/CTA)

// ---------------- scratch (static device allocations; no cudaMalloc) ----------------
__device__ float g_Q[B_*T_*DM_];          // 8 MB projected Q, layout [(b*T+t)][h*D+d]
__device__ float g_K[B_*T_*DM_];          // 8 MB
__device__ float g_V[B_*T_*DM_];          // 8 MB
__device__ float g_Zp[KC_*BH_*T_];        // partial Z = sum exp(s)
__device__ float g_Sp[KC_*BH_*T_];        // partial S = sum exp(s)*s
__device__ int   g_top[BH_*U_];           // top-3 query indices per (b,h)
__device__ float g_attp[BH_*U_*NCH_*D_];  // per-chunk partial P@V
__device__ float g_zc[BH_*U_*NCH_];       // per-chunk partial Z

// =====================================================================
// Fused projection GEMMs:  Y = X @ W^T + bias, for (q,Wq),(k,Wk),(v,Wv)
// selected by blockIdx.z. M=4096, N=512, K=512.
// BM=BN=128, BK=16, 256 threads, 8x8 per thread, k-major smem tiles.
// =====================================================================
__global__ __launch_bounds__(256) void proj3_kernel(
    const float* __restrict__ q,  const float* __restrict__ k,  const float* __restrict__ v,
    const float* __restrict__ Wq, const float* __restrict__ Wk, const float* __restrict__ Wv,
    const float* __restrict__ bq, const float* __restrict__ bk, const float* __restrict__ bv,
    float* __restrict__ Qp, float* __restrict__ Kp, float* __restrict__ Vp)
{
    const float* X; const float* W; const float* bias; float* Y;
    if (blockIdx.z == 0)      { X = q; W = Wq; bias = bq; Y = Qp; }
    else if (blockIdx.z == 1) { X = k; W = Wk; bias = bk; Y = Kp; }
    else                      { X = v; W = Wv; bias = bv; Y = Vp; }

    __shared__ float As[16][132];   // k-major: As[k][m]
    __shared__ float Bs[16][132];   // k-major: Bs[k][n]

    const int m0 = blockIdx.x * 128;
    const int n0 = blockIdx.y * 128;
    const int tid = threadIdx.x;
    const int tx = tid & 15;
    const int ty = tid >> 4;
    const int lr = tid >> 2;        // 0..63
    const int lc = (tid & 3) * 4;   // 0,4,8,12

    float acc[8][8];
#pragma unroll
    for (int i = 0; i < 8; i++)
#pragma unroll
        for (int j = 0; j < 8; j++) acc[i][j] = 0.f;

    for (int k0 = 0; k0 < DM_; k0 += 16) {
        float4 x0 = *(const float4*)&X[(size_t)(m0 + lr)      * DM_ + k0 + lc];
        float4 x1 = *(const float4*)&X[(size_t)(m0 + lr + 64) * DM_ + k0 + lc];
        float4 w0 = *(const float4*)&W[(size_t)(n0 + lr)      * DM_ + k0 + lc];
        float4 w1 = *(const float4*)&W[(size_t)(n0 + lr + 64) * DM_ + k0 + lc];
        __syncthreads();
        As[lc+0][lr] = x0.x; As[lc+1][lr] = x0.y; As[lc+2][lr] = x0.z; As[lc+3][lr] = x0.w;
        As[lc+0][lr+64] = x1.x; As[lc+1][lr+64] = x1.y; As[lc+2][lr+64] = x1.z; As[lc+3][lr+64] = x1.w;
        Bs[lc+0][lr] = w0.x; Bs[lc+1][lr] = w0.y; Bs[lc+2][lr] = w0.z; Bs[lc+3][lr] = w0.w;
        Bs[lc+0][lr+64] = w1.x; Bs[lc+1][lr+64] = w1.y; Bs[lc+2][lr+64] = w1.z; Bs[lc+3][lr+64] = w1.w;
        __syncthreads();

#pragma unroll
        for (int kk = 0; kk < 16; kk++) {
            float4 a0 = *(float4*)&As[kk][ty * 8];
            float4 a1 = *(float4*)&As[kk][ty * 8 + 4];
            float4 b0 = *(float4*)&Bs[kk][tx * 8];
            float4 b1 = *(float4*)&Bs[kk][tx * 8 + 4];
            float a[8] = {a0.x,a0.y,a0.z,a0.w,a1.x,a1.y,a1.z,a1.w};
            float b[8] = {b0.x,b0.y,b0.z,b0.w,b1.x,b1.y,b1.z,b1.w};
#pragma unroll
            for (int i = 0; i < 8; i++)
#pragma unroll
                for (int j = 0; j < 8; j++) acc[i][j] += a[i] * b[j];
        }
    }

    float bb[8];
#pragma unroll
    for (int j = 0; j < 8; j++) bb[j] = bias[n0 + tx * 8 + j];
#pragma unroll
    for (int i = 0; i < 8; i++) {
        int row = m0 + ty * 8 + i;
        float4 o0 = make_float4(acc[i][0]+bb[0], acc[i][1]+bb[1], acc[i][2]+bb[2], acc[i][3]+bb[3]);
        float4 o1 = make_float4(acc[i][4]+bb[4], acc[i][5]+bb[5], acc[i][6]+bb[6], acc[i][7]+bb[7]);
        *(float4*)&Y[(size_t)row * DM_ + n0 + tx * 8]     = o0;
        *(float4*)&Y[(size_t)row * DM_ + n0 + tx * 8 + 4] = o1;
    }
}

// =====================================================================
// KL accumulators: per (bh, q-tile of 128, k-half of 1024):
// streaming Z = sum exp(s), S = sum exp(s)*s over the k-half.
// =====================================================================
__global__ __launch_bounds__(256) void kl_kernel()
{
    extern __shared__ float sm[];
    float (*Qs)[132] = (float (*)[132])sm;
    float (*Ks)[132] = (float (*)[132])(sm + 64 * 132);

    const int bh = blockIdx.x;
    const int b = bh >> 3, h = bh & 7;
    const int q0 = blockIdx.y * 128;
    const int kc = blockIdx.z;
    const int kbase = kc * (T_ / KC_);
    const int tid = threadIdx.x;
    const int tx = tid & 15;
    const int ty = tid >> 4;
    const int lr = tid >> 2;        // 0..63
    const int lc = (tid & 3) * 4;   // 0,4,8,12

    const float* Qb = g_Q + (size_t)(b * T_) * DM_ + h * D_;
    const float* Kb = g_K + (size_t)(b * T_) * DM_ + h * D_;

#pragma unroll
    for (int half = 0; half < 2; half++) {
        int r = lr + half * 64;
#pragma unroll
        for (int ic = 0; ic < 4; ic++) {
            int c = lc + ic * 16;
            float4 t = *(const float4*)&Qb[(size_t)(q0 + r) * DM_ + c];
            Qs[c+0][r] = t.x; Qs[c+1][r] = t.y; Qs[c+2][r] = t.z; Qs[c+3][r] = t.w;
        }
    }

    float Zr[8], Sr[8];
#pragma unroll
    for (int i = 0; i < 8; i++) { Zr[i] = 0.f; Sr[i] = 0.f; }

    for (int kt = 0; kt < T_ / KC_; kt += 128) {
        float4 p0[4];
#pragma unroll
        for (int ic = 0; ic < 4; ic++)
            p0[ic] = *(const float4*)&Kb[(size_t)(kbase + kt + lr) * DM_ + lc + ic * 16];
        __syncthreads();
#pragma unroll
        for (int ic = 0; ic < 4; ic++) {
            int c = lc + ic * 16;
            Ks[c+0][lr] = p0[ic].x; Ks[c+1][lr] = p0[ic].y; Ks[c+2][lr] = p0[ic].z; Ks[c+3][lr] = p0[ic].w;
        }
#pragma unroll
        for (int ic = 0; ic < 4; ic++) {
            int c = lc + ic * 16;
            float4 t = *(const float4*)&Kb[(size_t)(kbase + kt + lr + 64) * DM_ + c];
            Ks[c+0][lr+64] = t.x; Ks[c+1][lr+64] = t.y; Ks[c+2][lr+64] = t.z; Ks[c+3][lr+64] = t.w;
        }
        __syncthreads();

        float acc[8][8];
#pragma unroll
        for (int i = 0; i < 8; i++)
#pragma unroll
            for (int j = 0; j < 8; j++) acc[i][j] = 0.f;

#pragma unroll 16
        for (int dd = 0; dd < 64; dd++) {
            float4 a0 = *(float4*)&Qs[dd][ty * 8];
            float4 a1 = *(float4*)&Qs[dd][ty * 8 + 4];
            float4 b0 = *(float4*)&Ks[dd][tx * 8];
            float4 b1 = *(float4*)&Ks[dd][tx * 8 + 4];
            float a[8] = {a0.x,a0.y,a0.z,a0.w,a1.x,a1.y,a1.z,a1.w};
            float bf[8] = {b0.x,b0.y,b0.z,b0.w,b1.x,b1.y,b1.z,b1.w};
#pragma unroll
            for (int i = 0; i < 8; i++)
#pragma unroll
                for (int j = 0; j < 8; j++) acc[i][j] += a[i] * bf[j];
        }

#pragma unroll
        for (int i = 0; i < 8; i++)
#pragma unroll
            for (int j = 0; j < 8; j++) {
                float s = acc[i][j] * 0.125f;
                float e = __expf(s);
                Zr[i] += e;
                Sr[i] += e * s;
            }
    }

#pragma unroll
    for (int i = 0; i < 8; i++) {
        float z = Zr[i], s = Sr[i];
#pragma unroll
        for (int off = 1; off < 16; off <<= 1) {
            z += __shfl_xor_sync(0xffffffffu, z, off);
            s += __shfl_xor_sync(0xffffffffu, s, off);
        }
        if (tx == 0) {
            int qi = q0 + ty * 8 + i;
            g_Zp[(kc * BH_ + bh) * T_ + qi] = z;
            g_Sp[(kc * BH_ + bh) * T_ + qi] = s;
        }
    }
}

// =====================================================================
// Top-3 per (b,h): combine partials -> KL, then 3 masked-argmax passes.
// =====================================================================
__global__ __launch_bounds__(256) void topk_kernel()
{
    __shared__ float skl[T_];
    __shared__ float sv[256];
    __shared__ int   si[256];
    const int bh = blockIdx.x;
    const int tid = threadIdx.x;
    const float LOGU = logf(1.0f / (float)T_ + 1e-10f);
    for (int i = tid; i < T_; i += 256) {
        float z = g_Zp[bh * T_ + i] + g_Zp[(BH_ + bh) * T_ + i];
        float s = g_Sp[bh * T_ + i] + g_Sp[(BH_ + bh) * T_ + i];
        skl[i] = s / z - __logf(z) - LOGU;
    }
    __syncthreads();
    for (int r = 0; r < U_; r++) {
        float bv = -1e30f; int bi = T_;
        for (int i = tid; i < T_; i += 256) {
            float v = skl[i];
            if (v > bv) { bv = v; bi = i; }
        }
        sv[tid] = bv; si[tid] = bi;
        __syncthreads();
        for (int st = 128; st > 0; st >>= 1) {
            if (tid < st) {
                float ov = sv[tid + st]; int oi = si[tid + st];
                if (ov > sv[tid] || (ov == sv[tid] && oi < si[tid])) { sv[tid] = ov; si[tid] = oi; }
            }
            __syncthreads();
        }
        if (tid == 0) { g_top[bh * U_ + r] = si[0]; skl[si[0]] = -1e30f; }
        __syncthreads();
    }
}

// =====================================================================
// Reduced attention, chunked: grid (48, NCH_). Each CTA handles 256 keys
// of one (b,h,u): one thread per key (dot in registers, no shuffles),
// then partial P@V over its 256 keys. Partials combined in scatter_kernel.
// =====================================================================
__global__ __launch_bounds__(256) void sparse_attn_kernel()
{
    __shared__ float qs[64];
    __shared__ float e[256];
    __shared__ float red[8];
    __shared__ float pb[4][64];

    const int bid = blockIdx.x;           // 0..47  (bh*U_+u)
    const int ch  = blockIdx.y;           // 0..7
    const int bh = bid / U_;
    const int b = bh >> 3, h = bh & 7;
    const int t = g_top[bid];
    const int tid = threadIdx.x;
    const int warp = tid >> 5, lane = tid & 31;

    const float* Qb = g_Q + ((size_t)(b * T_) + t) * DM_ + h * D_;
    if (tid < 16) *(float4*)&qs[tid * 4] = *(const float4*)&Qb[tid * 4];
    __syncthreads();

    // one thread per key: full 64-d dot product in registers
    const int kk = ch * 256 + tid;
    const float* Krow = g_K + ((size_t)(b * T_) + kk) * DM_ + h * D_;
    float dot = 0.f;
#pragma unroll
    for (int i = 0; i < 16; i++) {
        float4 kv = *(const float4*)&Krow[i * 4];
        float4 qv = *(const float4*)&qs[i * 4];
        dot += kv.x * qv.x + kv.y * qv.y + kv.z * qv.z + kv.w * qv.w;
    }
    float s = dot * 0.125f;
    if (!(s == s)) s = -10000.f;            // nan_to_num
    s = fminf(fmaxf(s, -10000.f), 10000.f); // clip
    float ev = expf(s);
    e[tid] = ev;

    // partial Z for this chunk
    float zr = ev;
#pragma unroll
    for (int off = 16; off > 0; off >>= 1) zr += __shfl_xor_sync(0xffffffffu, zr, off);
    if (lane == 0) red[warp] = zr;
    __syncthreads();
    if (tid == 0) {
        float z = 0.f;
        for (int w = 0; w < 8; w++) z += red[w];
        g_zc[bid * NCH_ + ch] = z;
    }

    // partial P@V over this chunk's 256 keys: thread (c,d) sums 64 keys
    const int d = tid & 63, c = tid >> 6;
    const float* Vb = g_V + ((size_t)(b * T_) + ch * 256 + c * 64) * DM_ + h * D_ + d;
    float o = 0.f;
#pragma unroll 8
    for (int j = 0; j < 64; j++) o += e[c * 64 + j] * Vb[(size_t)j * DM_];
    pb[c][d] = o;
    __syncthreads();
    if (tid < 64)
        g_attp[(bid * NCH_ + ch) * D_ + tid] =
            pb[0][tid] + pb[1][tid] + pb[2][tid] + pb[3][tid];
}

// =====================================================================
// Output: fill with bo, then add the 48 selected-row contributions
// (combining the per-chunk attention partials inline).
// =====================================================================
__global__ void init_out_kernel(float* __restrict__ out, const float* __restrict__ bo)
{
    int idx = blockIdx.x * 256 + threadIdx.x;
    if (idx < B_ * T_ * DM_) out[idx] = bo[idx & (DM_ - 1)];
}

__global__ __launch_bounds__(512) void scatter_kernel(
    const float* __restrict__ Wo, float* __restrict__ out)
{
    __shared__ float att[64];
    const int bid = blockIdx.x;      // 0..47
    const int bh = bid / U_;
    const int b = bh >> 3, h = bh & 7;
    const int t = g_top[bid];
    const int j = threadIdx.x;
    if (j < 64) {
        float z = 0.f, o = 0.f;
#pragma unroll
        for (int c = 0; c < NCH_; c++) {
            z += g_zc[bid * NCH_ + c];
            o += g_attp[(bid * NCH_ + c) * D_ + j];
        }
        att[j] = o / z;
    }
    __syncthreads();
    const float* w = Wo + (size_t)j * DM_ + h * D_;
    float a = 0.f;
#pragma unroll
    for (int d = 0; d < 64; d++) a += att[d] * w[d];
    atomicAdd(&out[((size_t)b * T_ + t) * DM_ + j], a);
}

// =====================================================================
extern "C" void kernel_launch(void* const* d_in, const int* in_sizes, int n_in,
                              void* d_out, int out_size)
{
    const float* query = (const float*)d_in[0];
    const float* key   = (const float*)d_in[1];
    const float* value = (const float*)d_in[2];
    const float* Wq    = (const float*)d_in[3];
    const float* bq    = (const float*)d_in[4];
    const float* Wk    = (const float*)d_in[5];
    const float* bk    = (const float*)d_in[6];
    const float* Wv    = (const float*)d_in[7];
    const float* bv    = (const float*)d_in[8];
    const float* Wo    = (const float*)d_in[9];
    const float* bo    = (const float*)d_in[10];
    float* out = (float*)d_out;

    float *Qp, *Kp, *Vp;
    cudaGetSymbolAddress((void**)&Qp, g_Q);
    cudaGetSymbolAddress((void**)&Kp, g_K);
    cudaGetSymbolAddress((void**)&Vp, g_V);

    cudaFuncSetAttribute(kl_kernel, cudaFuncAttributeMaxDynamicSharedMemorySize,
                         2 * 64 * 132 * 4);

    dim3 pg(32, 4, 3);   // 4096/128 x 512/128 x {q,k,v}
    proj3_kernel<<<pg, 256>>>(query, key, value, Wq, Wk, Wv, bq, bk, bv, Qp, Kp, Vp);

    dim3 kg(BH_, T_ / 128, KC_);  // (16, 16, 2)
    kl_kernel<<<kg, 256, 2 * 64 * 132 * 4>>>();

    topk_kernel<<<BH_, 256>>>();

    dim3 sg(BH_ * U_, NCH_);      // (48, 8)
    sparse_attn_kernel<<<sg, 256>>>();

    init_out_kernel<<<(B_ * T_ * DM_ + 255) / 256, 256>>>(out, bo);
    scatter_kernel<<<BH_ * U_, 512>>>(Wo, out);
}

// round 8
// speedup vs baseline: 2.3907x; 1.3333x over previous
#include <cuda_runtime.h>
#include <cuda_bf16.h>
#include <cstdint>
#include <math.h>

#define B_   2
#define T_   2048
#define DM_  512
#define H_   8
#define D_   64
#define BH_  (B_*H_)
#define U_   3      // int(0.4 * ln(2048)) = 3 selected queries per (b,h)
#define KC_  2      // k-split for kl kernel
#define NCH_ 8      // key-chunk split for sparse attention

// ---------------- scratch (static device allocations; no cudaMalloc) ----------------
__device__ float g_Q[B_*T_*DM_];          // projected Q fp32
__device__ float g_K[B_*T_*DM_];
__device__ float g_V[B_*T_*DM_];
__device__ __nv_bfloat16 g_Qh[B_*T_*DM_]; // bf16 copies for tensor-core KL
__device__ __nv_bfloat16 g_Kh[B_*T_*DM_];
__device__ float g_Zp[KC_*BH_*T_];        // partial Z = sum exp(s)
__device__ float g_Sp[KC_*BH_*T_];        // partial S = sum exp(s)*s
__device__ int   g_top[BH_*U_];
__device__ float g_attp[BH_*U_*NCH_*D_];
__device__ float g_zc[BH_*U_*NCH_];

// =====================================================================
// Fused projection GEMMs + bf16 emission for Q/K.
// =====================================================================
__global__ __launch_bounds__(256) void proj3_kernel(
    const float* __restrict__ q,  const float* __restrict__ k,  const float* __restrict__ v,
    const float* __restrict__ Wq, const float* __restrict__ Wk, const float* __restrict__ Wv,
    const float* __restrict__ bq, const float* __restrict__ bk, const float* __restrict__ bv,
    float* __restrict__ Qp, float* __restrict__ Kp, float* __restrict__ Vp)
{
    const float* X; const float* W; const float* bias; float* Y; __nv_bfloat16* Yh;
    if (blockIdx.z == 0)      { X = q; W = Wq; bias = bq; Y = Qp; Yh = g_Qh; }
    else if (blockIdx.z == 1) { X = k; W = Wk; bias = bk; Y = Kp; Yh = g_Kh; }
    else                      { X = v; W = Wv; bias = bv; Y = Vp; Yh = 0; }

    __shared__ float As[16][132];
    __shared__ float Bs[16][132];

    const int m0 = blockIdx.x * 128;
    const int n0 = blockIdx.y * 128;
    const int tid = threadIdx.x;
    const int tx = tid & 15;
    const int ty = tid >> 4;
    const int lr = tid >> 2;
    const int lc = (tid & 3) * 4;

    float acc[8][8];
#pragma unroll
    for (int i = 0; i < 8; i++)
#pragma unroll
        for (int j = 0; j < 8; j++) acc[i][j] = 0.f;

    for (int k0 = 0; k0 < DM_; k0 += 16) {
        float4 x0 = *(const float4*)&X[(size_t)(m0 + lr)      * DM_ + k0 + lc];
        float4 x1 = *(const float4*)&X[(size_t)(m0 + lr + 64) * DM_ + k0 + lc];
        float4 w0 = *(const float4*)&W[(size_t)(n0 + lr)      * DM_ + k0 + lc];
        float4 w1 = *(const float4*)&W[(size_t)(n0 + lr + 64) * DM_ + k0 + lc];
        __syncthreads();
        As[lc+0][lr] = x0.x; As[lc+1][lr] = x0.y; As[lc+2][lr] = x0.z; As[lc+3][lr] = x0.w;
        As[lc+0][lr+64] = x1.x; As[lc+1][lr+64] = x1.y; As[lc+2][lr+64] = x1.z; As[lc+3][lr+64] = x1.w;
        Bs[lc+0][lr] = w0.x; Bs[lc+1][lr] = w0.y; Bs[lc+2][lr] = w0.z; Bs[lc+3][lr] = w0.w;
        Bs[lc+0][lr+64] = w1.x; Bs[lc+1][lr+64] = w1.y; Bs[lc+2][lr+64] = w1.z; Bs[lc+3][lr+64] = w1.w;
        __syncthreads();

#pragma unroll
        for (int kk = 0; kk < 16; kk++) {
            float4 a0 = *(float4*)&As[kk][ty * 8];
            float4 a1 = *(float4*)&As[kk][ty * 8 + 4];
            float4 b0 = *(float4*)&Bs[kk][tx * 8];
            float4 b1 = *(float4*)&Bs[kk][tx * 8 + 4];
            float a[8] = {a0.x,a0.y,a0.z,a0.w,a1.x,a1.y,a1.z,a1.w};
            float b[8] = {b0.x,b0.y,b0.z,b0.w,b1.x,b1.y,b1.z,b1.w};
#pragma unroll
            for (int i = 0; i < 8; i++)
#pragma unroll
                for (int j = 0; j < 8; j++) acc[i][j] += a[i] * b[j];
        }
    }

    float bb[8];
#pragma unroll
    for (int j = 0; j < 8; j++) bb[j] = bias[n0 + tx * 8 + j];
#pragma unroll
    for (int i = 0; i < 8; i++) {
        int row = m0 + ty * 8 + i;
        float o[8];
#pragma unroll
        for (int j = 0; j < 8; j++) o[j] = acc[i][j] + bb[j];
        *(float4*)&Y[(size_t)row * DM_ + n0 + tx * 8]     = make_float4(o[0],o[1],o[2],o[3]);
        *(float4*)&Y[(size_t)row * DM_ + n0 + tx * 8 + 4] = make_float4(o[4],o[5],o[6],o[7]);
        if (Yh) {
            union { __nv_bfloat16 h[8]; uint4 u; } pk;
#pragma unroll
            for (int j = 0; j < 8; j++) pk.h[j] = __float2bfloat16(o[j]);
            *(uint4*)&Yh[(size_t)row * DM_ + n0 + tx * 8] = pk.u;
        }
    }
}

// =====================================================================
// KL via mma.sync bf16 (HMMA; base-PTX, legal on sm_100).
// Grid (BH, T/128, KC), 256 threads = 8 warps. Warp w owns q-rows
// [w*16, w*16+16) of the 128-row q tile, against all 128 keys per tile.
// m16n8k16 fragments loaded as 32-bit LDS from 72-padded smem tiles.
// Z,S accumulate in registers; quad-shuffle reduce; direct store.
// =====================================================================
__global__ __launch_bounds__(256) void kl_hmma_kernel()
{
    __shared__ __nv_bfloat16 Qs[128][72];  // 72-pad: conflict-free fragment loads
    __shared__ __nv_bfloat16 Ks[128][72];

    const int tid = threadIdx.x;
    const int w = tid >> 5, l = tid & 31;
    const int g = l >> 2, tg = l & 3;          // groupID / threadID-in-group
    const int bh = blockIdx.x, b = bh >> 3, h = bh & 7;
    const int q0 = blockIdx.y * 128;
    const int kc = blockIdx.z, kbase = kc * (T_ / KC_);
    const int NT = (T_ / KC_) / 128;           // 8 key tiles

    const __nv_bfloat16* Qh = g_Qh + (size_t)(b * T_) * DM_ + h * D_;
    const __nv_bfloat16* Kh = g_Kh + (size_t)(b * T_) * DM_ + h * D_;

    // load Q tile: each thread loads half a row (32 bf16 = 4 uint4)
    {
        const int r = tid >> 1, half = tid & 1;
        const uint4* src = (const uint4*)(Qh + (size_t)(q0 + r) * DM_ + half * 32);
        uint4* dst = (uint4*)&Qs[r][half * 32];
#pragma unroll
        for (int c = 0; c < 4; c++) dst[c] = src[c];
    }

    float acc[16][4];
#pragma unroll
    for (int ni = 0; ni < 16; ni++)
#pragma unroll
        for (int j = 0; j < 4; j++) acc[ni][j] = 0.f;

    float Z0 = 0.f, S0 = 0.f, Z1 = 0.f, S1 = 0.f;
    const int ar0 = w * 16 + g;      // A-frag rows for this lane
    const int ar1 = ar0 + 8;

    for (int it = 0; it < NT; it++) {
        __syncthreads();   // Ks consumers of prev tile done (and Qs ready on it=0)
        {
            const int r = tid >> 1, half = tid & 1;
            const uint4* src = (const uint4*)(Kh + (size_t)(kbase + it * 128 + r) * DM_ + half * 32);
            uint4* dst = (uint4*)&Ks[r][half * 32];
#pragma unroll
            for (int c = 0; c < 4; c++) dst[c] = src[c];
        }
        __syncthreads();

#pragma unroll
        for (int ks = 0; ks < 4; ks++) {
            const int k0 = ks * 16;
            unsigned a0 = *(const unsigned*)&Qs[ar0][k0 + tg * 2];
            unsigned a1 = *(const unsigned*)&Qs[ar1][k0 + tg * 2];
            unsigned a2 = *(const unsigned*)&Qs[ar0][k0 + tg * 2 + 8];
            unsigned a3 = *(const unsigned*)&Qs[ar1][k0 + tg * 2 + 8];
#pragma unroll
            for (int ni = 0; ni < 16; ni++) {
                unsigned b0 = *(const unsigned*)&Ks[ni * 8 + g][k0 + tg * 2];
                unsigned b1 = *(const unsigned*)&Ks[ni * 8 + g][k0 + tg * 2 + 8];
                asm volatile(
                    "mma.sync.aligned.m16n8k16.row.col.f32.bf16.bf16.f32 "
                    "{%0,%1,%2,%3}, {%4,%5,%6,%7}, {%8,%9}, {%0,%1,%2,%3};"
                    : "+f"(acc[ni][0]), "+f"(acc[ni][1]), "+f"(acc[ni][2]), "+f"(acc[ni][3])
                    : "r"(a0), "r"(a1), "r"(a2), "r"(a3), "r"(b0), "r"(b1));
            }
        }

        // epilogue: exp-accumulate this tile's scores, reset accumulators
#pragma unroll
        for (int ni = 0; ni < 16; ni++) {
            float s0 = acc[ni][0] * 0.125f; float e0 = __expf(s0); Z0 += e0; S0 += e0 * s0;
            float s1 = acc[ni][1] * 0.125f; float e1 = __expf(s1); Z0 += e1; S0 += e1 * s1;
            float s2 = acc[ni][2] * 0.125f; float e2 = __expf(s2); Z1 += e2; S1 += e2 * s2;
            float s3 = acc[ni][3] * 0.125f; float e3 = __expf(s3); Z1 += e3; S1 += e3 * s3;
            acc[ni][0] = 0.f; acc[ni][1] = 0.f; acc[ni][2] = 0.f; acc[ni][3] = 0.f;
        }
    }

    // reduce across the 4 lanes of each quad (tg = low 2 lane bits)
#pragma unroll
    for (int off = 1; off < 4; off <<= 1) {
        Z0 += __shfl_xor_sync(0xffffffffu, Z0, off);
        S0 += __shfl_xor_sync(0xffffffffu, S0, off);
        Z1 += __shfl_xor_sync(0xffffffffu, Z1, off);
        S1 += __shfl_xor_sync(0xffffffffu, S1, off);
    }
    if (tg == 0) {
        const int base = (kc * BH_ + bh) * T_ + q0 + w * 16 + g;
        g_Zp[base]     = Z0;  g_Sp[base]     = S0;
        g_Zp[base + 8] = Z1;  g_Sp[base + 8] = S1;
    }
}

// =====================================================================
// Top-3 per (b,h): combine partials -> KL, then 3 masked-argmax passes.
// =====================================================================
__global__ __launch_bounds__(256) void topk_kernel()
{
    __shared__ float skl[T_];
    __shared__ float sv[256];
    __shared__ int   si[256];
    const int bh = blockIdx.x;
    const int tid = threadIdx.x;
    const float LOGU = logf(1.0f / (float)T_ + 1e-10f);
    for (int i = tid; i < T_; i += 256) {
        float z = g_Zp[bh * T_ + i] + g_Zp[(BH_ + bh) * T_ + i];
        float s = g_Sp[bh * T_ + i] + g_Sp[(BH_ + bh) * T_ + i];
        skl[i] = s / z - __logf(z) - LOGU;
    }
    __syncthreads();
    for (int r = 0; r < U_; r++) {
        float bv = -1e30f; int bi = T_;
        for (int i = tid; i < T_; i += 256) {
            float v = skl[i];
            if (v > bv) { bv = v; bi = i; }
        }
        sv[tid] = bv; si[tid] = bi;
        __syncthreads();
        for (int st = 128; st > 0; st >>= 1) {
            if (tid < st) {
                float ov = sv[tid + st]; int oi = si[tid + st];
                if (ov > sv[tid] || (ov == sv[tid] && oi < si[tid])) { sv[tid] = ov; si[tid] = oi; }
            }
            __syncthreads();
        }
        if (tid == 0) { g_top[bh * U_ + r] = si[0]; skl[si[0]] = -1e30f; }
        __syncthreads();
    }
}

// =====================================================================
// Reduced attention (fp32 path): grid (48, NCH_).
// =====================================================================
__global__ __launch_bounds__(256) void sparse_attn_kernel()
{
    __shared__ float qs[64];
    __shared__ float e[256];
    __shared__ float red[8];
    __shared__ float pb[4][64];

    const int bid = blockIdx.x;
    const int ch  = blockIdx.y;
    const int bh = bid / U_;
    const int b = bh >> 3, h = bh & 7;
    const int t = g_top[bid];
    const int tid = threadIdx.x;
    const int warp = tid >> 5, lane = tid & 31;

    const float* Qb = g_Q + ((size_t)(b * T_) + t) * DM_ + h * D_;
    if (tid < 16) *(float4*)&qs[tid * 4] = *(const float4*)&Qb[tid * 4];
    __syncthreads();

    const int kk = ch * 256 + tid;
    const float* Krow = g_K + ((size_t)(b * T_) + kk) * DM_ + h * D_;
    float dot = 0.f;
#pragma unroll
    for (int i = 0; i < 16; i++) {
        float4 kv = *(const float4*)&Krow[i * 4];
        float4 qv = *(const float4*)&qs[i * 4];
        dot += kv.x * qv.x + kv.y * qv.y + kv.z * qv.z + kv.w * qv.w;
    }
    float s = dot * 0.125f;
    if (!(s == s)) s = -10000.f;
    s = fminf(fmaxf(s, -10000.f), 10000.f);
    float ev = expf(s);
    e[tid] = ev;

    float zr = ev;
#pragma unroll
    for (int off = 16; off > 0; off >>= 1) zr += __shfl_xor_sync(0xffffffffu, zr, off);
    if (lane == 0) red[warp] = zr;
    __syncthreads();
    if (tid == 0) {
        float z = 0.f;
        for (int w = 0; w < 8; w++) z += red[w];
        g_zc[bid * NCH_ + ch] = z;
    }

    const int d = tid & 63, c = tid >> 6;
    const float* Vb = g_V + ((size_t)(b * T_) + ch * 256 + c * 64) * DM_ + h * D_ + d;
    float o = 0.f;
#pragma unroll 8
    for (int j = 0; j < 64; j++) o += e[c * 64 + j] * Vb[(size_t)j * DM_];
    pb[c][d] = o;
    __syncthreads();
    if (tid < 64)
        g_attp[(bid * NCH_ + ch) * D_ + tid] =
            pb[0][tid] + pb[1][tid] + pb[2][tid] + pb[3][tid];
}

// =====================================================================
// Output: fill with bo, then add the 48 selected-row contributions.
// =====================================================================
__global__ void init_out_kernel(float* __restrict__ out, const float* __restrict__ bo)
{
    int idx = blockIdx.x * 256 + threadIdx.x;
    if (idx < B_ * T_ * DM_) out[idx] = bo[idx & (DM_ - 1)];
}

__global__ __launch_bounds__(512) void scatter_kernel(
    const float* __restrict__ Wo, float* __restrict__ out)
{
    __shared__ float att[64];
    const int bid = blockIdx.x;
    const int bh = bid / U_;
    const int b = bh >> 3, h = bh & 7;
    const int t = g_top[bid];
    const int j = threadIdx.x;
    if (j < 64) {
        float z = 0.f, o = 0.f;
#pragma unroll
        for (int c = 0; c < NCH_; c++) {
            z += g_zc[bid * NCH_ + c];
            o += g_attp[(bid * NCH_ + c) * D_ + j];
        }
        att[j] = o / z;
    }
    __syncthreads();
    const float* w = Wo + (size_t)j * DM_ + h * D_;
    float a = 0.f;
#pragma unroll
    for (int d = 0; d < 64; d++) a += att[d] * w[d];
    atomicAdd(&out[((size_t)b * T_ + t) * DM_ + j], a);
}

// =====================================================================
extern "C" void kernel_launch(void* const* d_in, const int* in_sizes, int n_in,
                              void* d_out, int out_size)
{
    const float* query = (const float*)d_in[0];
    const float* key   = (const float*)d_in[1];
    const float* value = (const float*)d_in[2];
    const float* Wq    = (const float*)d_in[3];
    const float* bq    = (const float*)d_in[4];
    const float* Wk    = (const float*)d_in[5];
    const float* bk    = (const float*)d_in[6];
    const float* Wv    = (const float*)d_in[7];
    const float* bv    = (const float*)d_in[8];
    const float* Wo    = (const float*)d_in[9];
    const float* bo    = (const float*)d_in[10];
    float* out = (float*)d_out;

    float *Qp, *Kp, *Vp;
    cudaGetSymbolAddress((void**)&Qp, g_Q);
    cudaGetSymbolAddress((void**)&Kp, g_K);
    cudaGetSymbolAddress((void**)&Vp, g_V);

    dim3 pg(32, 4, 3);
    proj3_kernel<<<pg, 256>>>(query, key, value, Wq, Wk, Wv, bq, bk, bv, Qp, Kp, Vp);

    dim3 kg(BH_, T_ / 128, KC_);  // (16, 16, 2)
    kl_hmma_kernel<<<kg, 256>>>();

    topk_kernel<<<BH_, 256>>>();

    dim3 sg(BH_ * U_, NCH_);
    sparse_attn_kernel<<<sg, 256>>>();

    init_out_kernel<<<(B_ * T_ * DM_ + 255) / 256, 256>>>(out, bo);
    scatter_kernel<<<BH_ * U_, 512>>>(Wo, out);
}

// round 11
// speedup vs baseline: 3.9567x; 1.6551x over previous
#include <cuda_runtime.h>
#include <cuda_bf16.h>
#include <cstdint>
#include <math.h>

#define B_   2
#define T_   2048
#define DM_  512
#define H_   8
#define D_   64
#define BH_  (B_*H_)
#define U_   3      // int(0.4 * ln(2048)) = 3 selected queries per (b,h)
#define KC_  2      // k-split for kl kernel
#define NCH_ 8      // key-chunk split for sparse attention

// ---------------- scratch (static device allocations; no cudaMalloc) ----------------
__device__ float g_Q[B_*T_*DM_];          // projected Q fp32
__device__ float g_K[B_*T_*DM_];
__device__ float g_V[B_*T_*DM_];
__device__ __nv_bfloat16 g_Qh[B_*T_*DM_]; // bf16 copies for tensor-core KL
__device__ __nv_bfloat16 g_Kh[B_*T_*DM_];
__device__ float g_Zp[KC_*BH_*T_];        // partial Z = sum exp(s)
__device__ float g_Sp[KC_*BH_*T_];        // partial S = sum exp(s)*s
__device__ int   g_top[BH_*U_];
__device__ float g_attp[BH_*U_*NCH_*D_];
__device__ float g_zc[BH_*U_*NCH_];

__device__ __forceinline__ void mma_bf16(float* c, const unsigned* a, const unsigned* b) {
    asm volatile(
        "mma.sync.aligned.m16n8k16.row.col.f32.bf16.bf16.f32 "
        "{%0,%1,%2,%3}, {%4,%5,%6,%7}, {%8,%9}, {%0,%1,%2,%3};"
        : "+f"(c[0]), "+f"(c[1]), "+f"(c[2]), "+f"(c[3])
        : "r"(a[0]), "r"(a[1]), "r"(a[2]), "r"(a[3]), "r"(b[0]), "r"(b[1]));
}

// =====================================================================
// Fused projection GEMMs via split-bf16 HMMA (3-pass: hh + hl + lh).
// Y = X @ W^T + bias. Grid (32, 4, 3), 256 threads = 8 warps (2x4).
// CTA tile 128x128, BK=32. Warp tile 64x32 = 4x4 m16n8 frags.
// Error ~1e-5 rel (lo*lo term dropped). Also emits bf16 Q/K for kl.
// =====================================================================
__global__ __launch_bounds__(256) void proj3_kernel(
    const float* __restrict__ q,  const float* __restrict__ k,  const float* __restrict__ v,
    const float* __restrict__ Wq, const float* __restrict__ Wk, const float* __restrict__ Wv,
    const float* __restrict__ bq, const float* __restrict__ bk, const float* __restrict__ bv,
    float* __restrict__ Qp, float* __restrict__ Kp, float* __restrict__ Vp)
{
    const float* X; const float* W; const float* bias; float* Y; __nv_bfloat16* Yh;
    if (blockIdx.z == 0)      { X = q; W = Wq; bias = bq; Y = Qp; Yh = g_Qh; }
    else if (blockIdx.z == 1) { X = k; W = Wk; bias = bk; Y = Kp; Yh = g_Kh; }
    else                      { X = v; W = Wv; bias = bv; Y = Vp; Yh = 0; }

    __shared__ __nv_bfloat16 Xh[128][40], Xl[128][40];   // [row][k], +8 pad
    __shared__ __nv_bfloat16 Wh[128][40], Wl[128][40];

    const int m0 = blockIdx.x * 128;
    const int n0 = blockIdx.y * 128;
    const int tid = threadIdx.x;
    const int w = tid >> 5, l = tid & 31;
    const int g = l >> 2, tg = l & 3;
    const int wm = w >> 2;          // 0..1 -> m offset wm*64
    const int wn = w & 3;           // 0..3 -> n offset wn*32
    const int lr = tid >> 1;        // 0..127 load row
    const int lcb = (tid & 1) * 16; // 0 or 16

    float acc[4][4][4];
#pragma unroll
    for (int mi = 0; mi < 4; mi++)
#pragma unroll
        for (int ni = 0; ni < 4; ni++)
#pragma unroll
            for (int j = 0; j < 4; j++) acc[mi][ni][j] = 0.f;

    for (int kt = 0; kt < DM_; kt += 32) {
        float4 xv[4], wv[4];
#pragma unroll
        for (int c = 0; c < 4; c++) {
            xv[c] = *(const float4*)&X[(size_t)(m0 + lr) * DM_ + kt + lcb + c * 4];
            wv[c] = *(const float4*)&W[(size_t)(n0 + lr) * DM_ + kt + lcb + c * 4];
        }
        __syncthreads();   // prev tile consumed
#pragma unroll
        for (int c = 0; c < 4; c++) {
            const int idx = lcb + c * 4;
            float xs[4] = {xv[c].x, xv[c].y, xv[c].z, xv[c].w};
            float ws[4] = {wv[c].x, wv[c].y, wv[c].z, wv[c].w};
            __nv_bfloat16 xh[4], wh[4];
            float xr[4], wr[4];
#pragma unroll
            for (int e = 0; e < 4; e++) {
                xh[e] = __float2bfloat16(xs[e]);
                xr[e] = xs[e] - __bfloat162float(xh[e]);
                wh[e] = __float2bfloat16(ws[e]);
                wr[e] = ws[e] - __bfloat162float(wh[e]);
            }
            *(__nv_bfloat162*)&Xh[lr][idx]     = __nv_bfloat162(xh[0], xh[1]);
            *(__nv_bfloat162*)&Xh[lr][idx + 2] = __nv_bfloat162(xh[2], xh[3]);
            *(__nv_bfloat162*)&Xl[lr][idx]     = __floats2bfloat162_rn(xr[0], xr[1]);
            *(__nv_bfloat162*)&Xl[lr][idx + 2] = __floats2bfloat162_rn(xr[2], xr[3]);
            *(__nv_bfloat162*)&Wh[lr][idx]     = __nv_bfloat162(wh[0], wh[1]);
            *(__nv_bfloat162*)&Wh[lr][idx + 2] = __nv_bfloat162(wh[2], wh[3]);
            *(__nv_bfloat162*)&Wl[lr][idx]     = __floats2bfloat162_rn(wr[0], wr[1]);
            *(__nv_bfloat162*)&Wl[lr][idx + 2] = __floats2bfloat162_rn(wr[2], wr[3]);
        }
        __syncthreads();

#pragma unroll
        for (int ks = 0; ks < 2; ks++) {
            const int k0 = ks * 16;
            unsigned ah[4][4], al[4][4];
#pragma unroll
            for (int mi = 0; mi < 4; mi++) {
                const int r0 = wm * 64 + mi * 16 + g, r1 = r0 + 8;
                ah[mi][0] = *(const unsigned*)&Xh[r0][k0 + tg * 2];
                ah[mi][1] = *(const unsigned*)&Xh[r1][k0 + tg * 2];
                ah[mi][2] = *(const unsigned*)&Xh[r0][k0 + tg * 2 + 8];
                ah[mi][3] = *(const unsigned*)&Xh[r1][k0 + tg * 2 + 8];
                al[mi][0] = *(const unsigned*)&Xl[r0][k0 + tg * 2];
                al[mi][1] = *(const unsigned*)&Xl[r1][k0 + tg * 2];
                al[mi][2] = *(const unsigned*)&Xl[r0][k0 + tg * 2 + 8];
                al[mi][3] = *(const unsigned*)&Xl[r1][k0 + tg * 2 + 8];
            }
            unsigned bh[4][2], bl[4][2];
#pragma unroll
            for (int ni = 0; ni < 4; ni++) {
                const int col = wn * 32 + ni * 8 + g;
                bh[ni][0] = *(const unsigned*)&Wh[col][k0 + tg * 2];
                bh[ni][1] = *(const unsigned*)&Wh[col][k0 + tg * 2 + 8];
                bl[ni][0] = *(const unsigned*)&Wl[col][k0 + tg * 2];
                bl[ni][1] = *(const unsigned*)&Wl[col][k0 + tg * 2 + 8];
            }
#pragma unroll
            for (int mi = 0; mi < 4; mi++)
#pragma unroll
                for (int ni = 0; ni < 4; ni++) {
                    mma_bf16(acc[mi][ni], ah[mi], bh[ni]);
                    mma_bf16(acc[mi][ni], ah[mi], bl[ni]);
                    mma_bf16(acc[mi][ni], al[mi], bh[ni]);
                }
        }
    }

    // epilogue: add bias, store fp32 (+ bf16 for Q/K)
#pragma unroll
    for (int ni = 0; ni < 4; ni++) {
        const int col = n0 + wn * 32 + ni * 8 + tg * 2;
        const float b0 = bias[col], b1 = bias[col + 1];
#pragma unroll
        for (int mi = 0; mi < 4; mi++) {
            const int row0 = m0 + wm * 64 + mi * 16 + g, row1 = row0 + 8;
            float o00 = acc[mi][ni][0] + b0, o01 = acc[mi][ni][1] + b1;
            float o10 = acc[mi][ni][2] + b0, o11 = acc[mi][ni][3] + b1;
            *(float2*)&Y[(size_t)row0 * DM_ + col] = make_float2(o00, o01);
            *(float2*)&Y[(size_t)row1 * DM_ + col] = make_float2(o10, o11);
            if (Yh) {
                *(__nv_bfloat162*)&Yh[(size_t)row0 * DM_ + col] = __floats2bfloat162_rn(o00, o01);
                *(__nv_bfloat162*)&Yh[(size_t)row1 * DM_ + col] = __floats2bfloat162_rn(o10, o11);
            }
        }
    }
}

// =====================================================================
// KL via mma.sync bf16 (HMMA). Grid (BH, T/128, KC), 256 threads.
// =====================================================================
__global__ __launch_bounds__(256) void kl_hmma_kernel()
{
    __shared__ __nv_bfloat16 Qs[128][72];
    __shared__ __nv_bfloat16 Ks[128][72];

    const int tid = threadIdx.x;
    const int w = tid >> 5, l = tid & 31;
    const int g = l >> 2, tg = l & 3;
    const int bh = blockIdx.x, b = bh >> 3, h = bh & 7;
    const int q0 = blockIdx.y * 128;
    const int kc = blockIdx.z, kbase = kc * (T_ / KC_);
    const int NT = (T_ / KC_) / 128;

    const __nv_bfloat16* Qh = g_Qh + (size_t)(b * T_) * DM_ + h * D_;
    const __nv_bfloat16* Kh = g_Kh + (size_t)(b * T_) * DM_ + h * D_;

    {
        const int r = tid >> 1, half = tid & 1;
        const uint4* src = (const uint4*)(Qh + (size_t)(q0 + r) * DM_ + half * 32);
        uint4* dst = (uint4*)&Qs[r][half * 32];
#pragma unroll
        for (int c = 0; c < 4; c++) dst[c] = src[c];
    }

    float acc[16][4];
#pragma unroll
    for (int ni = 0; ni < 16; ni++)
#pragma unroll
        for (int j = 0; j < 4; j++) acc[ni][j] = 0.f;

    float Z0 = 0.f, S0 = 0.f, Z1 = 0.f, S1 = 0.f;
    const int ar0 = w * 16 + g;
    const int ar1 = ar0 + 8;

    for (int it = 0; it < NT; it++) {
        __syncthreads();
        {
            const int r = tid >> 1, half = tid & 1;
            const uint4* src = (const uint4*)(Kh + (size_t)(kbase + it * 128 + r) * DM_ + half * 32);
            uint4* dst = (uint4*)&Ks[r][half * 32];
#pragma unroll
            for (int c = 0; c < 4; c++) dst[c] = src[c];
        }
        __syncthreads();

#pragma unroll
        for (int ks = 0; ks < 4; ks++) {
            const int k0 = ks * 16;
            unsigned a[4];
            a[0] = *(const unsigned*)&Qs[ar0][k0 + tg * 2];
            a[1] = *(const unsigned*)&Qs[ar1][k0 + tg * 2];
            a[2] = *(const unsigned*)&Qs[ar0][k0 + tg * 2 + 8];
            a[3] = *(const unsigned*)&Qs[ar1][k0 + tg * 2 + 8];
#pragma unroll
            for (int ni = 0; ni < 16; ni++) {
                unsigned bb[2];
                bb[0] = *(const unsigned*)&Ks[ni * 8 + g][k0 + tg * 2];
                bb[1] = *(const unsigned*)&Ks[ni * 8 + g][k0 + tg * 2 + 8];
                mma_bf16(acc[ni], a, bb);
            }
        }

#pragma unroll
        for (int ni = 0; ni < 16; ni++) {
            float s0 = acc[ni][0] * 0.125f; float e0 = __expf(s0); Z0 += e0; S0 += e0 * s0;
            float s1 = acc[ni][1] * 0.125f; float e1 = __expf(s1); Z0 += e1; S0 += e1 * s1;
            float s2 = acc[ni][2] * 0.125f; float e2 = __expf(s2); Z1 += e2; S1 += e2 * s2;
            float s3 = acc[ni][3] * 0.125f; float e3 = __expf(s3); Z1 += e3; S1 += e3 * s3;
            acc[ni][0] = 0.f; acc[ni][1] = 0.f; acc[ni][2] = 0.f; acc[ni][3] = 0.f;
        }
    }

#pragma unroll
    for (int off = 1; off < 4; off <<= 1) {
        Z0 += __shfl_xor_sync(0xffffffffu, Z0, off);
        S0 += __shfl_xor_sync(0xffffffffu, S0, off);
        Z1 += __shfl_xor_sync(0xffffffffu, Z1, off);
        S1 += __shfl_xor_sync(0xffffffffu, S1, off);
    }
    if (tg == 0) {
        const int base = (kc * BH_ + bh) * T_ + q0 + w * 16 + g;
        g_Zp[base]     = Z0;  g_Sp[base]     = S0;
        g_Zp[base + 8] = Z1;  g_Sp[base + 8] = S1;
    }
}

// =====================================================================
// Top-3 per (b,h): combine partials -> KL, then 3 masked-argmax passes.
// =====================================================================
__global__ __launch_bounds__(256) void topk_kernel()
{
    __shared__ float skl[T_];
    __shared__ float sv[256];
    __shared__ int   si[256];
    const int bh = blockIdx.x;
    const int tid = threadIdx.x;
    const float LOGU = logf(1.0f / (float)T_ + 1e-10f);
    for (int i = tid; i < T_; i += 256) {
        float z = g_Zp[bh * T_ + i] + g_Zp[(BH_ + bh) * T_ + i];
        float s = g_Sp[bh * T_ + i] + g_Sp[(BH_ + bh) * T_ + i];
        skl[i] = s / z - __logf(z) - LOGU;
    }
    __syncthreads();
    for (int r = 0; r < U_; r++) {
        float bv = -1e30f; int bi = T_;
        for (int i = tid; i < T_; i += 256) {
            float v = skl[i];
            if (v > bv) { bv = v; bi = i; }
        }
        sv[tid] = bv; si[tid] = bi;
        __syncthreads();
        for (int st = 128; st > 0; st >>= 1) {
            if (tid < st) {
                float ov = sv[tid + st]; int oi = si[tid + st];
                if (ov > sv[tid] || (ov == sv[tid] && oi < si[tid])) { sv[tid] = ov; si[tid] = oi; }
            }
            __syncthreads();
        }
        if (tid == 0) { g_top[bh * U_ + r] = si[0]; skl[si[0]] = -1e30f; }
        __syncthreads();
    }
}

// =====================================================================
// Reduced attention (fp32 path): grid (48, NCH_).
// =====================================================================
__global__ __launch_bounds__(256) void sparse_attn_kernel()
{
    __shared__ float qs[64];
    __shared__ float e[256];
    __shared__ float red[8];
    __shared__ float pb[4][64];

    const int bid = blockIdx.x;
    const int ch  = blockIdx.y;
    const int bh = bid / U_;
    const int b = bh >> 3, h = bh & 7;
    const int t = g_top[bid];
    const int tid = threadIdx.x;
    const int warp = tid >> 5, lane = tid & 31;

    const float* Qb = g_Q + ((size_t)(b * T_) + t) * DM_ + h * D_;
    if (tid < 16) *(float4*)&qs[tid * 4] = *(const float4*)&Qb[tid * 4];
    __syncthreads();

    const int kk = ch * 256 + tid;
    const float* Krow = g_K + ((size_t)(b * T_) + kk) * DM_ + h * D_;
    float dot = 0.f;
#pragma unroll
    for (int i = 0; i < 16; i++) {
        float4 kv = *(const float4*)&Krow[i * 4];
        float4 qv = *(const float4*)&qs[i * 4];
        dot += kv.x * qv.x + kv.y * qv.y + kv.z * qv.z + kv.w * qv.w;
    }
    float s = dot * 0.125f;
    if (!(s == s)) s = -10000.f;
    s = fminf(fmaxf(s, -10000.f), 10000.f);
    float ev = expf(s);
    e[tid] = ev;

    float zr = ev;
#pragma unroll
    for (int off = 16; off > 0; off >>= 1) zr += __shfl_xor_sync(0xffffffffu, zr, off);
    if (lane == 0) red[warp] = zr;
    __syncthreads();
    if (tid == 0) {
        float z = 0.f;
        for (int w = 0; w < 8; w++) z += red[w];
        g_zc[bid * NCH_ + ch] = z;
    }

    const int d = tid & 63, c = tid >> 6;
    const float* Vb = g_V + ((size_t)(b * T_) + ch * 256 + c * 64) * DM_ + h * D_ + d;
    float o = 0.f;
#pragma unroll 8
    for (int j = 0; j < 64; j++) o += e[c * 64 + j] * Vb[(size_t)j * DM_];
    pb[c][d] = o;
    __syncthreads();
    if (tid < 64)
        g_attp[(bid * NCH_ + ch) * D_ + tid] =
            pb[0][tid] + pb[1][tid] + pb[2][tid] + pb[3][tid];
}

// =====================================================================
// Output: fill with bo, then add the 48 selected-row contributions.
// =====================================================================
__global__ void init_out_kernel(float* __restrict__ out, const float* __restrict__ bo)
{
    int idx = blockIdx.x * 256 + threadIdx.x;
    if (idx < B_ * T_ * DM_) out[idx] = bo[idx & (DM_ - 1)];
}

__global__ __launch_bounds__(512) void scatter_kernel(
    const float* __restrict__ Wo, float* __restrict__ out)
{
    __shared__ float att[64];
    const int bid = blockIdx.x;
    const int bh = bid / U_;
    const int b = bh >> 3, h = bh & 7;
    const int t = g_top[bid];
    const int j = threadIdx.x;
    if (j < 64) {
        float z = 0.f, o = 0.f;
#pragma unroll
        for (int c = 0; c < NCH_; c++) {
            z += g_zc[bid * NCH_ + c];
            o += g_attp[(bid * NCH_ + c) * D_ + j];
        }
        att[j] = o / z;
    }
    __syncthreads();
    const float* w = Wo + (size_t)j * DM_ + h * D_;
    float a = 0.f;
#pragma unroll
    for (int d = 0; d < 64; d++) a += att[d] * w[d];
    atomicAdd(&out[((size_t)b * T_ + t) * DM_ + j], a);
}

// =====================================================================
extern "C" void kernel_launch(void* const* d_in, const int* in_sizes, int n_in,
                              void* d_out, int out_size)
{
    const float* query = (const float*)d_in[0];
    const float* key   = (const float*)d_in[1];
    const float* value = (const float*)d_in[2];
    const float* Wq    = (const float*)d_in[3];
    const float* bq    = (const float*)d_in[4];
    const float* Wk    = (const float*)d_in[5];
    const float* bk    = (const float*)d_in[6];
    const float* Wv    = (const float*)d_in[7];
    const float* bv    = (const float*)d_in[8];
    const float* Wo    = (const float*)d_in[9];
    const float* bo    = (const float*)d_in[10];
    float* out = (float*)d_out;

    float *Qp, *Kp, *Vp;
    cudaGetSymbolAddress((void**)&Qp, g_Q);
    cudaGetSymbolAddress((void**)&Kp, g_K);
    cudaGetSymbolAddress((void**)&Vp, g_V);

    dim3 pg(32, 4, 3);
    proj3_kernel<<<pg, 256>>>(query, key, value, Wq, Wk, Wv, bq, bk, bv, Qp, Kp, Vp);

    dim3 kg(BH_, T_ / 128, KC_);  // (16, 16, 2)
    kl_hmma_kernel<<<kg, 256>>>();

    topk_kernel<<<BH_, 256>>>();

    dim3 sg(BH_ * U_, NCH_);
    sparse_attn_kernel<<<sg, 256>>>();

    init_out_kernel<<<(B_ * T_ * DM_ + 255) / 256, 256>>>(out, bo);
    scatter_kernel<<<BH_ * U_, 512>>>(Wo, out);
}

// round 12
// speedup vs baseline: 4.0514x; 1.0239x over previous
#include <cuda_runtime.h>
#include <cuda_bf16.h>
#include <cstdint>
#include <math.h>

#define B_   2
#define T_   2048
#define DM_  512
#define H_   8
#define D_   64
#define BH_  (B_*H_)
#define U_   3      // int(0.4 * ln(2048)) = 3 selected queries per (b,h)
#define KC_  2      // k-split for kl kernel
#define NCH_ 8      // key-chunk split for sparse attention

// ---------------- scratch (static device allocations; no cudaMalloc) ----------------
__device__ float g_Q[B_*T_*DM_];          // projected Q fp32
__device__ float g_K[B_*T_*DM_];
__device__ float g_V[B_*T_*DM_];
__device__ __nv_bfloat16 g_Qh[B_*T_*DM_]; // bf16 copies for tensor-core KL
__device__ __nv_bfloat16 g_Kh[B_*T_*DM_];
__device__ float g_Zp[KC_*BH_*T_];        // partial Z = sum exp(s)
__device__ float g_Sp[KC_*BH_*T_];        // partial S = sum exp(s)*s
__device__ int   g_top[BH_*U_];
__device__ float g_attp[BH_*U_*NCH_*D_];
__device__ float g_zc[BH_*U_*NCH_];

__device__ __forceinline__ void mma_bf16(float* c, const unsigned* a, const unsigned* b) {
    asm volatile(
        "mma.sync.aligned.m16n8k16.row.col.f32.bf16.bf16.f32 "
        "{%0,%1,%2,%3}, {%4,%5,%6,%7}, {%8,%9}, {%0,%1,%2,%3};"
        : "+f"(c[0]), "+f"(c[1]), "+f"(c[2]), "+f"(c[3])
        : "r"(a[0]), "r"(a[1]), "r"(a[2]), "r"(a[3]), "r"(b[0]), "r"(b[1]));
}
__device__ __forceinline__ unsigned smem_u32(const void* p) {
    unsigned a;
    asm("{ .reg .u64 t; cvta.to.shared.u64 t, %1; cvt.u32.u64 %0, t; }" : "=r"(a) : "l"(p));
    return a;
}
__device__ __forceinline__ void ldmx4(unsigned& r0, unsigned& r1, unsigned& r2, unsigned& r3,
                                      unsigned addr) {
    asm volatile("ldmatrix.sync.aligned.m8n8.x4.shared.b16 {%0,%1,%2,%3}, [%4];"
                 : "=r"(r0), "=r"(r1), "=r"(r2), "=r"(r3) : "r"(addr));
}
__device__ __forceinline__ void cp16(unsigned dst, const void* src) {
    asm volatile("cp.async.ca.shared.global [%0], [%1], 16;" :: "r"(dst), "l"(src));
}
__device__ __forceinline__ void cp_commit()  { asm volatile("cp.async.commit_group;" ::: "memory"); }
__device__ __forceinline__ void cp_wait1()   { asm volatile("cp.async.wait_group 1;" ::: "memory"); }
__device__ __forceinline__ void cp_wait0()   { asm volatile("cp.async.wait_group 0;" ::: "memory"); }

// =====================================================================
// Fused projection GEMMs via split-bf16 HMMA (3-pass: hh + hl + lh).
// (unchanged from the 193us version)
// =====================================================================
__global__ __launch_bounds__(256) void proj3_kernel(
    const float* __restrict__ q,  const float* __restrict__ k,  const float* __restrict__ v,
    const float* __restrict__ Wq, const float* __restrict__ Wk, const float* __restrict__ Wv,
    const float* __restrict__ bq, const float* __restrict__ bk, const float* __restrict__ bv,
    float* __restrict__ Qp, float* __restrict__ Kp, float* __restrict__ Vp)
{
    const float* X; const float* W; const float* bias; float* Y; __nv_bfloat16* Yh;
    if (blockIdx.z == 0)      { X = q; W = Wq; bias = bq; Y = Qp; Yh = g_Qh; }
    else if (blockIdx.z == 1) { X = k; W = Wk; bias = bk; Y = Kp; Yh = g_Kh; }
    else                      { X = v; W = Wv; bias = bv; Y = Vp; Yh = 0; }

    __shared__ __nv_bfloat16 Xh[128][40], Xl[128][40];   // [row][k], +8 pad
    __shared__ __nv_bfloat16 Wh[128][40], Wl[128][40];

    const int m0 = blockIdx.x * 128;
    const int n0 = blockIdx.y * 128;
    const int tid = threadIdx.x;
    const int w = tid >> 5, l = tid & 31;
    const int g = l >> 2, tg = l & 3;
    const int wm = w >> 2;
    const int wn = w & 3;
    const int lr = tid >> 1;
    const int lcb = (tid & 1) * 16;

    float acc[4][4][4];
#pragma unroll
    for (int mi = 0; mi < 4; mi++)
#pragma unroll
        for (int ni = 0; ni < 4; ni++)
#pragma unroll
            for (int j = 0; j < 4; j++) acc[mi][ni][j] = 0.f;

    for (int kt = 0; kt < DM_; kt += 32) {
        float4 xv[4], wv[4];
#pragma unroll
        for (int c = 0; c < 4; c++) {
            xv[c] = *(const float4*)&X[(size_t)(m0 + lr) * DM_ + kt + lcb + c * 4];
            wv[c] = *(const float4*)&W[(size_t)(n0 + lr) * DM_ + kt + lcb + c * 4];
        }
        __syncthreads();
#pragma unroll
        for (int c = 0; c < 4; c++) {
            const int idx = lcb + c * 4;
            float xs[4] = {xv[c].x, xv[c].y, xv[c].z, xv[c].w};
            float ws[4] = {wv[c].x, wv[c].y, wv[c].z, wv[c].w};
            __nv_bfloat16 xh[4], wh[4];
            float xr[4], wr[4];
#pragma unroll
            for (int e = 0; e < 4; e++) {
                xh[e] = __float2bfloat16(xs[e]);
                xr[e] = xs[e] - __bfloat162float(xh[e]);
                wh[e] = __float2bfloat16(ws[e]);
                wr[e] = ws[e] - __bfloat162float(wh[e]);
            }
            *(__nv_bfloat162*)&Xh[lr][idx]     = __nv_bfloat162(xh[0], xh[1]);
            *(__nv_bfloat162*)&Xh[lr][idx + 2] = __nv_bfloat162(xh[2], xh[3]);
            *(__nv_bfloat162*)&Xl[lr][idx]     = __floats2bfloat162_rn(xr[0], xr[1]);
            *(__nv_bfloat162*)&Xl[lr][idx + 2] = __floats2bfloat162_rn(xr[2], xr[3]);
            *(__nv_bfloat162*)&Wh[lr][idx]     = __nv_bfloat162(wh[0], wh[1]);
            *(__nv_bfloat162*)&Wh[lr][idx + 2] = __nv_bfloat162(wh[2], wh[3]);
            *(__nv_bfloat162*)&Wl[lr][idx]     = __floats2bfloat162_rn(wr[0], wr[1]);
            *(__nv_bfloat162*)&Wl[lr][idx + 2] = __floats2bfloat162_rn(wr[2], wr[3]);
        }
        __syncthreads();

#pragma unroll
        for (int ks = 0; ks < 2; ks++) {
            const int k0 = ks * 16;
            unsigned ah[4][4], al[4][4];
#pragma unroll
            for (int mi = 0; mi < 4; mi++) {
                const int r0 = wm * 64 + mi * 16 + g, r1 = r0 + 8;
                ah[mi][0] = *(const unsigned*)&Xh[r0][k0 + tg * 2];
                ah[mi][1] = *(const unsigned*)&Xh[r1][k0 + tg * 2];
                ah[mi][2] = *(const unsigned*)&Xh[r0][k0 + tg * 2 + 8];
                ah[mi][3] = *(const unsigned*)&Xh[r1][k0 + tg * 2 + 8];
                al[mi][0] = *(const unsigned*)&Xl[r0][k0 + tg * 2];
                al[mi][1] = *(const unsigned*)&Xl[r1][k0 + tg * 2];
                al[mi][2] = *(const unsigned*)&Xl[r0][k0 + tg * 2 + 8];
                al[mi][3] = *(const unsigned*)&Xl[r1][k0 + tg * 2 + 8];
            }
            unsigned bh[4][2], bl[4][2];
#pragma unroll
            for (int ni = 0; ni < 4; ni++) {
                const int col = wn * 32 + ni * 8 + g;
                bh[ni][0] = *(const unsigned*)&Wh[col][k0 + tg * 2];
                bh[ni][1] = *(const unsigned*)&Wh[col][k0 + tg * 2 + 8];
                bl[ni][0] = *(const unsigned*)&Wl[col][k0 + tg * 2];
                bl[ni][1] = *(const unsigned*)&Wl[col][k0 + tg * 2 + 8];
            }
#pragma unroll
            for (int mi = 0; mi < 4; mi++)
#pragma unroll
                for (int ni = 0; ni < 4; ni++) {
                    mma_bf16(acc[mi][ni], ah[mi], bh[ni]);
                    mma_bf16(acc[mi][ni], ah[mi], bl[ni]);
                    mma_bf16(acc[mi][ni], al[mi], bh[ni]);
                }
        }
    }

#pragma unroll
    for (int ni = 0; ni < 4; ni++) {
        const int col = n0 + wn * 32 + ni * 8 + tg * 2;
        const float b0 = bias[col], b1 = bias[col + 1];
#pragma unroll
        for (int mi = 0; mi < 4; mi++) {
            const int row0 = m0 + wm * 64 + mi * 16 + g, row1 = row0 + 8;
            float o00 = acc[mi][ni][0] + b0, o01 = acc[mi][ni][1] + b1;
            float o10 = acc[mi][ni][2] + b0, o11 = acc[mi][ni][3] + b1;
            *(float2*)&Y[(size_t)row0 * DM_ + col] = make_float2(o00, o01);
            *(float2*)&Y[(size_t)row1 * DM_ + col] = make_float2(o10, o11);
            if (Yh) {
                *(__nv_bfloat162*)&Yh[(size_t)row0 * DM_ + col] = __floats2bfloat162_rn(o00, o01);
                *(__nv_bfloat162*)&Yh[(size_t)row1 * DM_ + col] = __floats2bfloat162_rn(o10, o11);
            }
        }
    }
}

// =====================================================================
// KL via HMMA + ldmatrix fragments + cp.async double-buffered K tiles.
// Grid (BH, T/128, KC), 256 threads. Dyn smem: Qs(18432) + 2x Ks(18432)
// = 55296 B. Row pitch 72 bf16 = 144 B (ldmatrix conflict-free).
// =====================================================================
__global__ __launch_bounds__(256) void kl_hmma_kernel()
{
    extern __shared__ __align__(16) char smraw[];
    const unsigned smb = smem_u32(smraw);
    const unsigned QSB = smb;
    const unsigned KSB0 = smb + 18432u, KSB1 = smb + 36864u;

    const int tid = threadIdx.x;
    const int w = tid >> 5, l = tid & 31;
    const int g = l >> 2, tg = l & 3;
    const int bh = blockIdx.x, b = bh >> 3, h = bh & 7;
    const int q0 = blockIdx.y * 128;
    const int kc = blockIdx.z, kbase = kc * (T_ / KC_);
    const int NT = (T_ / KC_) / 128;   // 8 key tiles

    const __nv_bfloat16* Qh = g_Qh + (size_t)(b * T_) * DM_ + h * D_;
    const __nv_bfloat16* Kh = g_Kh + (size_t)(b * T_) * DM_ + h * D_;

    const int cr = tid >> 1, chalf = tid & 1;      // copy row / half
    const unsigned cdst_off = (unsigned)(cr * 144 + chalf * 64);

    // group 0: Q tile + K tile 0
    {
        const __nv_bfloat16* src = Qh + (size_t)(q0 + cr) * DM_ + chalf * 32;
#pragma unroll
        for (int c = 0; c < 4; c++) cp16(QSB + cdst_off + c * 16, src + c * 8);
        const __nv_bfloat16* ksrc = Kh + (size_t)(kbase + cr) * DM_ + chalf * 32;
#pragma unroll
        for (int c = 0; c < 4; c++) cp16(KSB0 + cdst_off + c * 16, ksrc + c * 8);
        cp_commit();
    }
    // group 1: K tile 1
    {
        const __nv_bfloat16* ksrc = Kh + (size_t)(kbase + 128 + cr) * DM_ + chalf * 32;
#pragma unroll
        for (int c = 0; c < 4; c++) cp16(KSB1 + cdst_off + c * 16, ksrc + c * 8);
        cp_commit();
    }

    float acc[16][4];
#pragma unroll
    for (int ni = 0; ni < 16; ni++)
#pragma unroll
        for (int j = 0; j < 4; j++) acc[ni][j] = 0.f;

    float Z0 = 0.f, S0 = 0.f, Z1 = 0.f, S1 = 0.f;

    // ldmatrix per-lane address components (byte offsets)
    const unsigned a_row_off = (unsigned)((w * 16 + (l & 15)) * 144 + ((l >> 4) << 3) * 2);
    const unsigned b_row_off = (unsigned)((((l >> 4) << 3) + (l & 7)) * 144 + (((l >> 3) & 1) << 3) * 2);

    for (int it = 0; it < NT; it++) {
        if (it + 1 < NT) cp_wait1(); else cp_wait0();
        __syncthreads();

        const unsigned kb = (it & 1) ? KSB1 : KSB0;
#pragma unroll
        for (int ks = 0; ks < 4; ks++) {
            const unsigned k0b = (unsigned)(ks * 32);   // 16 bf16 = 32 B
            unsigned a[4];
            ldmx4(a[0], a[1], a[2], a[3], QSB + a_row_off + k0b);
#pragma unroll
            for (int nb = 0; nb < 8; nb++) {
                unsigned b0, b1, b2, b3;
                ldmx4(b0, b1, b2, b3, kb + b_row_off + (unsigned)(nb * 16 * 144) + k0b);
                unsigned bb0[2] = {b0, b1}, bb1[2] = {b2, b3};
                mma_bf16(acc[nb * 2],     a, bb0);
                mma_bf16(acc[nb * 2 + 1], a, bb1);
            }
        }

        // epilogue: exp-accumulate this tile's scores, reset accumulators
#pragma unroll
        for (int ni = 0; ni < 16; ni++) {
            float s0 = acc[ni][0] * 0.125f; float e0 = __expf(s0); Z0 += e0; S0 += e0 * s0;
            float s1 = acc[ni][1] * 0.125f; float e1 = __expf(s1); Z0 += e1; S0 += e1 * s1;
            float s2 = acc[ni][2] * 0.125f; float e2 = __expf(s2); Z1 += e2; S1 += e2 * s2;
            float s3 = acc[ni][3] * 0.125f; float e3 = __expf(s3); Z1 += e3; S1 += e3 * s3;
            acc[ni][0] = 0.f; acc[ni][1] = 0.f; acc[ni][2] = 0.f; acc[ni][3] = 0.f;
        }
        __syncthreads();   // buffer (it&1) fully consumed by all warps

        if (it + 2 < NT) {
            const unsigned dst = ((it & 1) ? KSB1 : KSB0) + cdst_off;
            const __nv_bfloat16* ksrc = Kh + (size_t)(kbase + (it + 2) * 128 + cr) * DM_ + chalf * 32;
#pragma unroll
            for (int c = 0; c < 4; c++) cp16(dst + c * 16, ksrc + c * 8);
            cp_commit();
        }
    }

    // reduce across the 4 lanes of each quad
#pragma unroll
    for (int off = 1; off < 4; off <<= 1) {
        Z0 += __shfl_xor_sync(0xffffffffu, Z0, off);
        S0 += __shfl_xor_sync(0xffffffffu, S0, off);
        Z1 += __shfl_xor_sync(0xffffffffu, Z1, off);
        S1 += __shfl_xor_sync(0xffffffffu, S1, off);
    }
    if (tg == 0) {
        const int base = (kc * BH_ + bh) * T_ + q0 + w * 16 + g;
        g_Zp[base]     = Z0;  g_Sp[base]     = S0;
        g_Zp[base + 8] = Z1;  g_Sp[base + 8] = S1;
    }
}

// =====================================================================
// Top-3 per (b,h): combine partials -> KL, then 3 masked-argmax passes.
// =====================================================================
__global__ __launch_bounds__(256) void topk_kernel()
{
    __shared__ float skl[T_];
    __shared__ float sv[256];
    __shared__ int   si[256];
    const int bh = blockIdx.x;
    const int tid = threadIdx.x;
    const float LOGU = logf(1.0f / (float)T_ + 1e-10f);
    for (int i = tid; i < T_; i += 256) {
        float z = g_Zp[bh * T_ + i] + g_Zp[(BH_ + bh) * T_ + i];
        float s = g_Sp[bh * T_ + i] + g_Sp[(BH_ + bh) * T_ + i];
        skl[i] = s / z - __logf(z) - LOGU;
    }
    __syncthreads();
    for (int r = 0; r < U_; r++) {
        float bv = -1e30f; int bi = T_;
        for (int i = tid; i < T_; i += 256) {
            float v = skl[i];
            if (v > bv) { bv = v; bi = i; }
        }
        sv[tid] = bv; si[tid] = bi;
        __syncthreads();
        for (int st = 128; st > 0; st >>= 1) {
            if (tid < st) {
                float ov = sv[tid + st]; int oi = si[tid + st];
                if (ov > sv[tid] || (ov == sv[tid] && oi < si[tid])) { sv[tid] = ov; si[tid] = oi; }
            }
            __syncthreads();
        }
        if (tid == 0) { g_top[bh * U_ + r] = si[0]; skl[si[0]] = -1e30f; }
        __syncthreads();
    }
}

// =====================================================================
// Reduced attention (fp32 path): grid (48, NCH_).
// =====================================================================
__global__ __launch_bounds__(256) void sparse_attn_kernel()
{
    __shared__ float qs[64];
    __shared__ float e[256];
    __shared__ float red[8];
    __shared__ float pb[4][64];

    const int bid = blockIdx.x;
    const int ch  = blockIdx.y;
    const int bh = bid / U_;
    const int b = bh >> 3, h = bh & 7;
    const int t = g_top[bid];
    const int tid = threadIdx.x;
    const int warp = tid >> 5, lane = tid & 31;

    const float* Qb = g_Q + ((size_t)(b * T_) + t) * DM_ + h * D_;
    if (tid < 16) *(float4*)&qs[tid * 4] = *(const float4*)&Qb[tid * 4];
    __syncthreads();

    const int kk = ch * 256 + tid;
    const float* Krow = g_K + ((size_t)(b * T_) + kk) * DM_ + h * D_;
    float dot = 0.f;
#pragma unroll
    for (int i = 0; i < 16; i++) {
        float4 kv = *(const float4*)&Krow[i * 4];
        float4 qv = *(const float4*)&qs[i * 4];
        dot += kv.x * qv.x + kv.y * qv.y + kv.z * qv.z + kv.w * qv.w;
    }
    float s = dot * 0.125f;
    if (!(s == s)) s = -10000.f;
    s = fminf(fmaxf(s, -10000.f), 10000.f);
    float ev = expf(s);
    e[tid] = ev;

    float zr = ev;
#pragma unroll
    for (int off = 16; off > 0; off >>= 1) zr += __shfl_xor_sync(0xffffffffu, zr, off);
    if (lane == 0) red[warp] = zr;
    __syncthreads();
    if (tid == 0) {
        float z = 0.f;
        for (int w = 0; w < 8; w++) z += red[w];
        g_zc[bid * NCH_ + ch] = z;
    }

    const int d = tid & 63, c = tid >> 6;
    const float* Vb = g_V + ((size_t)(b * T_) + ch * 256 + c * 64) * DM_ + h * D_ + d;
    float o = 0.f;
#pragma unroll 8
    for (int j = 0; j < 64; j++) o += e[c * 64 + j] * Vb[(size_t)j * DM_];
    pb[c][d] = o;
    __syncthreads();
    if (tid < 64)
        g_attp[(bid * NCH_ + ch) * D_ + tid] =
            pb[0][tid] + pb[1][tid] + pb[2][tid] + pb[3][tid];
}

// =====================================================================
// Output: fill with bo, then add the 48 selected-row contributions.
// =====================================================================
__global__ void init_out_kernel(float* __restrict__ out, const float* __restrict__ bo)
{
    int idx = blockIdx.x * 256 + threadIdx.x;
    if (idx < B_ * T_ * DM_) out[idx] = bo[idx & (DM_ - 1)];
}

__global__ __launch_bounds__(512) void scatter_kernel(
    const float* __restrict__ Wo, float* __restrict__ out)
{
    __shared__ float att[64];
    const int bid = blockIdx.x;
    const int bh = bid / U_;
    const int b = bh >> 3, h = bh & 7;
    const int t = g_top[bid];
    const int j = threadIdx.x;
    if (j < 64) {
        float z = 0.f, o = 0.f;
#pragma unroll
        for (int c = 0; c < NCH_; c++) {
            z += g_zc[bid * NCH_ + c];
            o += g_attp[(bid * NCH_ + c) * D_ + j];
        }
        att[j] = o / z;
    }
    __syncthreads();
    const float* w = Wo + (size_t)j * DM_ + h * D_;
    float a = 0.f;
#pragma unroll
    for (int d = 0; d < 64; d++) a += att[d] * w[d];
    atomicAdd(&out[((size_t)b * T_ + t) * DM_ + j], a);
}

// =====================================================================
extern "C" void kernel_launch(void* const* d_in, const int* in_sizes, int n_in,
                              void* d_out, int out_size)
{
    const float* query = (const float*)d_in[0];
    const float* key   = (const float*)d_in[1];
    const float* value = (const float*)d_in[2];
    const float* Wq    = (const float*)d_in[3];
    const float* bq    = (const float*)d_in[4];
    const float* Wk    = (const float*)d_in[5];
    const float* bk    = (const float*)d_in[6];
    const float* Wv    = (const float*)d_in[7];
    const float* bv    = (const float*)d_in[8];
    const float* Wo    = (const float*)d_in[9];
    const float* bo    = (const float*)d_in[10];
    float* out = (float*)d_out;

    float *Qp, *Kp, *Vp;
    cudaGetSymbolAddress((void**)&Qp, g_Q);
    cudaGetSymbolAddress((void**)&Kp, g_K);
    cudaGetSymbolAddress((void**)&Vp, g_V);

    const int KL_SMEM = 3 * 18432;  // 55296
    cudaFuncSetAttribute(kl_hmma_kernel, cudaFuncAttributeMaxDynamicSharedMemorySize, KL_SMEM);

    dim3 pg(32, 4, 3);
    proj3_kernel<<<pg, 256>>>(query, key, value, Wq, Wk, Wv, bq, bk, bv, Qp, Kp, Vp);

    dim3 kg(BH_, T_ / 128, KC_);  // (16, 16, 2)
    kl_hmma_kernel<<<kg, 256, KL_SMEM>>>();

    topk_kernel<<<BH_, 256>>>();

    dim3 sg(BH_ * U_, NCH_);
    sparse_attn_kernel<<<sg, 256>>>();

    init_out_kernel<<<(B_ * T_ * DM_ + 255) / 256, 256>>>(out, bo);
    scatter_kernel<<<BH_ * U_, 512>>>(Wo, out);
}